// round 11
// baseline (speedup 1.0000x reference)
#include <cuda_runtime.h>
#include <cuda_fp16.h>
#include <cstdint>

#define BB  32
#define SS  2048
#define DD  768
#define QDIM 256
#define ODIM 1024
#define STAGES 3
#define PITCH 40                     // halves per smem row (80B)
#define AROWS 64
#define BROWS 128
#define STGB  ((AROWS + BROWS) * PITCH * 2)   // 15360 bytes per stage

// -------- scratch (allocation-free: __device__ globals) --------
__device__ __half g_dataH[(size_t)BB * SS * DD];
__device__ __half g_W12h[2 * QDIM * DD];           // [W1; W2]
__device__ float  g_B12[2 * QDIM];                 // [b1; b2]
__device__ __half g_QKh[(size_t)BB * SS * 2 * QDIM]; // per row: Q[0:256] K[256:512]
__device__ __half g_KTh[(size_t)BB * QDIM * SS];   // K transposed [b][q][s]
__device__ __half g_EH [(size_t)BB * SS * SS];     // exp(scores) fp16 (256 MB)
__device__ float  g_RS [BB * SS];                  // row sums of exp
__device__ float  g_XMAX[BB * QDIM];               // fused maxpool result

__device__ __forceinline__ uint32_t smem_u32(const void* p) {
    uint32_t a;
    asm("{ .reg .u64 t; cvta.to.shared.u64 t, %1; cvt.u32.u64 %0, t; }" : "=r"(a) : "l"(p));
    return a;
}
__device__ __forceinline__ void cp16(uint32_t dst, const void* src) {
    asm volatile("cp.async.cg.shared.global [%0], [%1], 16;" :: "r"(dst), "l"(src));
}
#define CP_COMMIT() asm volatile("cp.async.commit_group;" ::: "memory")
#define CP_WAIT(n)  asm volatile("cp.async.wait_group %0;" :: "n"(n) : "memory")

__device__ __forceinline__ void ldsm4(uint32_t& r0, uint32_t& r1, uint32_t& r2,
                                      uint32_t& r3, uint32_t addr) {
    asm volatile("ldmatrix.sync.aligned.m8n8.x4.shared.b16 {%0,%1,%2,%3}, [%4];"
                 : "=r"(r0), "=r"(r1), "=r"(r2), "=r"(r3) : "r"(addr));
}

__device__ __forceinline__ void mma16(float* d, const uint32_t* a, const uint32_t* b) {
    asm volatile(
        "mma.sync.aligned.m16n8k16.row.col.f32.f16.f16.f32 "
        "{%0,%1,%2,%3}, {%4,%5,%6,%7}, {%8,%9}, {%0,%1,%2,%3};"
        : "+f"(d[0]), "+f"(d[1]), "+f"(d[2]), "+f"(d[3])
        : "r"(a[0]), "r"(a[1]), "r"(a[2]), "r"(a[3]), "r"(b[0]), "r"(b[1]));
}

// exact, order-independent float atomic max (init must be -inf)
__device__ __forceinline__ void atomicMaxF(float* a, float v) {
    if (v >= 0.f) atomicMax((int*)a, __float_as_int(v));
    else          atomicMin((unsigned int*)a, __float_as_uint(v));
}

// ============================================================================
// fp16 NT GEMM, cp.async 3-stage pipeline + ldmatrix fragments.
// CTA tile 64x128, k-chunk 32, 128 threads (4 warps 2m x 2n), warp tile 32x64.
// 4 CTAs/SM -> each SMSP hosts warps of 4 independent CTAs (de-lockstepped).
// A [M,K], B [N,K] fp16 row-major.
//   EPI=2: C fp16 + bias; if bn>=256 ALSO CT fp16 transposed per-batch
//          [QDIM][SS] at q = n-256 (merged QK projection)
//   EPI=3: C fp16 = exp(acc*scale); per-row sums atomically added to aux[b*SS+m]
//   EPI=4: no C store; X[m,n] = acc / aux[b*SS+n]; row-max over n fused:
//          atomicMaxF into xmax[b*QDIM+m]
// Smem rows padded to 40 halves (80B): conflict-free ldmatrix.
// Requires M%64==0, N%128==0, kdim%32==0.
// ============================================================================
template <int EPI>
__global__ __launch_bounds__(128, 4) void hgemm(
    const __half* __restrict__ A, const __half* __restrict__ B,
    const float* __restrict__ bias, void* __restrict__ Cv,
    __half* __restrict__ CT, float* __restrict__ aux, float* __restrict__ xmax,
    int lda, int ldb, int ldc, int kdim, float scale,
    size_t sA, size_t sB, size_t sC)
{
    extern __shared__ __half sm[];
    A += (size_t)blockIdx.z * sA;
    B += (size_t)blockIdx.z * sB;
    const int bm = blockIdx.y * 64;
    const int bn = blockIdx.x * 128;

    const int tid = threadIdx.x;
    const int lane = tid & 31, wid = tid >> 5;
    const int wm = wid & 1, wn = wid >> 1;      // warp 32m x 64n
    const int qd = lane >> 2, cc = lane & 3;

    // loaders
    const int arow = tid >> 1;                  // 0..63
    const int aseg = (tid & 1) * 16;            // halves
    const __half* pa = A + (size_t)(bm + arow) * lda + aseg;
    const __half* pb = B + (size_t)(bn + tid) * ldb;
    const uint32_t smb = smem_u32(sm);
    const uint32_t dA = smb + (uint32_t)(arow * PITCH + aseg) * 2;
    const uint32_t dB = smb + (uint32_t)((AROWS + tid) * PITCH) * 2;

    // ldmatrix per-lane offsets (relative to stage base, ks=0)
    uint32_t aoff[2], boff[4];
#pragma unroll
    for (int mt = 0; mt < 2; mt++)
        aoff[mt] = (uint32_t)(((wm * 32 + mt * 16 + (lane & 7) + (lane & 8)) * PITCH
                               + ((lane >> 4) * 8)) * 2);
#pragma unroll
    for (int np = 0; np < 4; np++)
        boff[np] = (uint32_t)(((AROWS + wn * 64 + np * 16 + (lane & 7)
                                + ((lane >> 4) * 8)) * PITCH + (lane & 8)) * 2);

    float acc[2][8][4];
#pragma unroll
    for (int i = 0; i < 2; i++)
#pragma unroll
        for (int j = 0; j < 8; j++)
#pragma unroll
            for (int r = 0; r < 4; r++) acc[i][j][r] = 0.f;

    const int nc = kdim >> 5;

    // prologue: stages 0..STAGES-2
#pragma unroll
    for (int s = 0; s < STAGES - 1; s++) {
        if (s < nc) {
            const size_t k0 = (size_t)s * 32;
            const uint32_t da = dA + s * STGB, db = dB + s * STGB;
            cp16(da,      pa + k0);
            cp16(da + 16, pa + k0 + 8);
#pragma unroll
            for (int i = 0; i < 4; i++) cp16(db + i * 16, pb + k0 + i * 8);
        }
        CP_COMMIT();
    }

    int st = 0;
    for (int ch = 0; ch < nc; ch++) {
        CP_WAIT(STAGES - 2);
        __syncthreads();   // stage st ready; everyone done reading prior stage

        // refill the stage freed by chunk ch-1
        {
            const int nxt = ch + STAGES - 1;
            if (nxt < nc) {
                int fs = st + STAGES - 1; if (fs >= STAGES) fs -= STAGES;
                const size_t k0 = (size_t)nxt * 32;
                const uint32_t da = dA + fs * STGB, db = dB + fs * STGB;
                cp16(da,      pa + k0);
                cp16(da + 16, pa + k0 + 8);
#pragma unroll
                for (int i = 0; i < 4; i++) cp16(db + i * 16, pb + k0 + i * 8);
            }
            CP_COMMIT();
        }

        const uint32_t sa = smb + (uint32_t)st * STGB;
#pragma unroll
        for (int ks = 0; ks < 2; ks++) {
            uint32_t af[2][4], bf[8][2];
#pragma unroll
            for (int mt = 0; mt < 2; mt++)
                ldsm4(af[mt][0], af[mt][1], af[mt][2], af[mt][3],
                      sa + aoff[mt] + ks * 32);
#pragma unroll
            for (int np = 0; np < 4; np++)
                ldsm4(bf[2 * np][0], bf[2 * np][1], bf[2 * np + 1][0],
                      bf[2 * np + 1][1], sa + boff[np] + ks * 32);
#pragma unroll
            for (int mt = 0; mt < 2; mt++)
#pragma unroll
                for (int nt = 0; nt < 8; nt++)
                    mma16(acc[mt][nt], af[mt], bf[nt]);
        }
        if (++st == STAGES) st = 0;
    }

    // ---- epilogue ----
    float inv[8][2];
    if (EPI == 4) {
#pragma unroll
        for (int nt = 0; nt < 8; nt++) {
            const int n0 = bn + wn * 64 + nt * 8 + cc * 2;
            inv[nt][0] = 1.0f / __ldg(&aux[blockIdx.z * SS + n0]);
            inv[nt][1] = 1.0f / __ldg(&aux[blockIdx.z * SS + n0 + 1]);
        }
    }
    float* srs = (float*)sm;   // EPI==3: per-CTA row sums (64 floats)
    if (EPI == 3) {
        __syncthreads();       // all warps done reading pipeline smem
        if (tid < 64) srs[tid] = 0.f;
        __syncthreads();
    }

#pragma unroll
    for (int mt = 0; mt < 2; mt++) {
        const int m0 = bm + wm * 32 + mt * 16 + qd;
        float rs0 = 0.f, rs1 = 0.f;               // EPI==3 row sums
        float mx0 = -INFINITY, mx1 = -INFINITY;   // EPI==4 row maxes
#pragma unroll
        for (int nt = 0; nt < 8; nt++) {
            const int n0 = bn + wn * 64 + nt * 8 + cc * 2;
            float c0 = acc[mt][nt][0] * scale;
            float c1 = acc[mt][nt][1] * scale;
            float c2 = acc[mt][nt][2] * scale;
            float c3 = acc[mt][nt][3] * scale;
            if (EPI == 4) {
                c0 *= inv[nt][0]; c1 *= inv[nt][1];
                c2 *= inv[nt][0]; c3 *= inv[nt][1];
                mx0 = fmaxf(mx0, fmaxf(c0, c1));
                mx1 = fmaxf(mx1, fmaxf(c2, c3));
            } else if (EPI == 3) {
                c0 = __expf(c0); c1 = __expf(c1);
                c2 = __expf(c2); c3 = __expf(c3);
                rs0 += c0 + c1; rs1 += c2 + c3;
                __half2 h0 = __floats2half2_rn(c0, c1);
                __half2 h1 = __floats2half2_rn(c2, c3);
                __half* Ch = (__half*)Cv + (size_t)blockIdx.z * sC;
                *(__half2*)(Ch + (size_t)m0 * ldc + n0)       = h0;
                *(__half2*)(Ch + (size_t)(m0 + 8) * ldc + n0) = h1;
            } else {  // EPI == 2: merged QK projection
                const float bx = bias[n0], by = bias[n0 + 1];
                c0 += bx; c1 += by; c2 += bx; c3 += by;
                __half2 h0 = __floats2half2_rn(c0, c1);
                __half2 h1 = __floats2half2_rn(c2, c3);
                __half* Ch = (__half*)Cv + (size_t)blockIdx.z * sC;
                *(__half2*)(Ch + (size_t)m0 * ldc + n0)       = h0;
                *(__half2*)(Ch + (size_t)(m0 + 8) * ldc + n0) = h1;
                if (bn + wn * 64 >= 256) {   // K columns -> transposed copy
                    const int b0 = m0 >> 11, s0 = m0 & (SS - 1);
                    __half* t = CT + ((size_t)b0 * QDIM + (n0 - 256)) * SS + s0;
                    t[0]      = __low2half(h0);
                    t[SS]     = __high2half(h0);
                    t[8]      = __low2half(h1);
                    t[SS + 8] = __high2half(h1);
                }
            }
        }
        if (EPI == 3) {
            rs0 += __shfl_xor_sync(0xffffffffu, rs0, 1);
            rs0 += __shfl_xor_sync(0xffffffffu, rs0, 2);
            rs1 += __shfl_xor_sync(0xffffffffu, rs1, 1);
            rs1 += __shfl_xor_sync(0xffffffffu, rs1, 2);
            if (cc == 0) {
                atomicAdd(&srs[wm * 32 + mt * 16 + qd],     rs0);
                atomicAdd(&srs[wm * 32 + mt * 16 + qd + 8], rs1);
            }
        }
        if (EPI == 4) {
            mx0 = fmaxf(mx0, __shfl_xor_sync(0xffffffffu, mx0, 1));
            mx0 = fmaxf(mx0, __shfl_xor_sync(0xffffffffu, mx0, 2));
            mx1 = fmaxf(mx1, __shfl_xor_sync(0xffffffffu, mx1, 1));
            mx1 = fmaxf(mx1, __shfl_xor_sync(0xffffffffu, mx1, 2));
            if (cc == 0) {
                atomicMaxF(&xmax[blockIdx.z * QDIM + m0],     mx0);
                atomicMaxF(&xmax[blockIdx.z * QDIM + m0 + 8], mx1);
            }
        }
    }
    if (EPI == 3) {
        __syncthreads();
        if (tid < 64) atomicAdd(&aux[blockIdx.z * SS + bm + tid], srs[tid]);
    }
}

// ============================================================================
// init: RS=0 (64 blocks), XMAX=-inf (8 blocks), B12 = [b1;b2] (2 blocks)
// ============================================================================
__global__ __launch_bounds__(256) void init_aux(
    float* __restrict__ rs, float* __restrict__ xmax,
    const float* __restrict__ b1, const float* __restrict__ b2,
    float* __restrict__ b12)
{
    if (blockIdx.x < 64) {
        const int i = blockIdx.x * 1024 + threadIdx.x * 4;
        *(float4*)(rs + i) = make_float4(0.f, 0.f, 0.f, 0.f);
    } else if (blockIdx.x < 72) {
        const int i = (blockIdx.x - 64) * 1024 + threadIdx.x * 4;
        const float ninf = -INFINITY;
        *(float4*)(xmax + i) = make_float4(ninf, ninf, ninf, ninf);
    } else if (blockIdx.x == 72) {
        b12[threadIdx.x] = b1[threadIdx.x];
    } else {
        b12[256 + threadIdx.x] = b2[threadIdx.x];
    }
}

// ============================================================================
// fp32 -> fp16 conversion (n % 8 == 0)
// ============================================================================
__global__ __launch_bounds__(256) void f2h_kernel(
    const float* __restrict__ s, __half* __restrict__ d, size_t n)
{
    const size_t i = ((size_t)blockIdx.x * 256 + threadIdx.x) * 8;
    if (i + 8 <= n) {
        float4 a = *(const float4*)(s + i);
        float4 b = *(const float4*)(s + i + 4);
        uint4 o;
        __half2 h;
        h = __floats2half2_rn(a.x, a.y); o.x = *(uint32_t*)&h;
        h = __floats2half2_rn(a.z, a.w); o.y = *(uint32_t*)&h;
        h = __floats2half2_rn(b.x, b.y); o.z = *(uint32_t*)&h;
        h = __floats2half2_rn(b.z, b.w); o.w = *(uint32_t*)&h;
        *(uint4*)(d + i) = o;
    }
}

// ============================================================================
__global__ __launch_bounds__(256) void final_head(
    const float* __restrict__ W3, const float* __restrict__ b3,
    float* __restrict__ out)
{
    const int b = blockIdx.x;
    const int tid = threadIdx.x;
    __shared__ float xs[QDIM];
    xs[tid] = g_XMAX[b * QDIM + tid];
    __syncthreads();

#pragma unroll
    for (int kk = 0; kk < 4; kk++) {
        const int o = tid + kk * 256;
        const float4* w = (const float4*)(W3 + (size_t)o * QDIM);
        float acc = 0.f;
#pragma unroll
        for (int qq = 0; qq < QDIM / 4; qq++) {
            float4 wv = w[qq];
            acc += wv.x * xs[qq * 4 + 0] + wv.y * xs[qq * 4 + 1]
                 + wv.z * xs[qq * 4 + 2] + wv.w * xs[qq * 4 + 3];
        }
        out[(size_t)b * ODIM + o] = fmaxf(acc + b3[o], 0.f);
    }
}

// ============================================================================
extern "C" void kernel_launch(void* const* d_in, const int* in_sizes, int n_in,
                              void* d_out, int out_size)
{
    const float* data = (const float*)d_in[0];
    /* d_in[1] = seq_len: unused by the reference */
    const float* W1 = (const float*)d_in[2];
    const float* b1 = (const float*)d_in[3];
    const float* W2 = (const float*)d_in[4];
    const float* b2 = (const float*)d_in[5];
    const float* W3 = (const float*)d_in[6];
    const float* b3 = (const float*)d_in[7];
    float* out = (float*)d_out;

    __half *dataH, *W12h, *QKh, *KTh, *EH;
    float *B12, *RS, *XMAX;
    cudaGetSymbolAddress((void**)&dataH, g_dataH);
    cudaGetSymbolAddress((void**)&W12h, g_W12h);
    cudaGetSymbolAddress((void**)&B12,  g_B12);
    cudaGetSymbolAddress((void**)&QKh,  g_QKh);
    cudaGetSymbolAddress((void**)&KTh,  g_KTh);
    cudaGetSymbolAddress((void**)&EH,   g_EH);
    cudaGetSymbolAddress((void**)&RS,   g_RS);
    cudaGetSymbolAddress((void**)&XMAX, g_XMAX);

    const int SMEM = STAGES * STGB;   // 46080 B
    cudaFuncSetAttribute(hgemm<2>, cudaFuncAttributeMaxDynamicSharedMemorySize, SMEM);
    cudaFuncSetAttribute(hgemm<3>, cudaFuncAttributeMaxDynamicSharedMemorySize, SMEM);
    cudaFuncSetAttribute(hgemm<4>, cudaFuncAttributeMaxDynamicSharedMemorySize, SMEM);

    const size_t strQK = (size_t)SS * 2 * QDIM;   // per-batch stride in QKh
    const size_t strKT = (size_t)QDIM * SS;
    const size_t strSC = (size_t)SS * SS;
    const float  inv_sqrt_qd = 1.0f / 16.0f;

    // 0) convert inputs to fp16; init RS=0, XMAX=-inf, B12=[b1;b2]
    const size_t nd = (size_t)BB * SS * DD;
    f2h_kernel<<<(unsigned)(nd / (256 * 8)), 256>>>(data, dataH, nd);
    f2h_kernel<<<(QDIM * DD) / (256 * 8), 256>>>(W1, W12h, QDIM * DD);
    f2h_kernel<<<(QDIM * DD) / (256 * 8), 256>>>(W2, W12h + QDIM * DD, QDIM * DD);
    init_aux<<<74, 256>>>(RS, XMAX, b1, b2, B12);

    // 1) QK = data @ [W1;W2]^T + [b1;b2] -> fp16 [BS][512]; K part also -> KTh
    hgemm<2><<<dim3(512 / 128, (BB * SS) / 64, 1), 128, SMEM>>>(
        dataH, W12h, B12, QKh, KTh, nullptr, nullptr,
        DD, DD, 2 * QDIM, DD, 1.0f, 0, 0, 0);

    // 2) E[b] = exp((K[b] @ Q[b]^T) / 16) -> fp16, rowsums into RS
    hgemm<3><<<dim3(SS / 128, SS / 64, BB), 128, SMEM>>>(
        QKh + 256, QKh, nullptr, EH, nullptr, RS, nullptr,
        2 * QDIM, 2 * QDIM, SS, QDIM, inv_sqrt_qd, strQK, strQK, strSC);

    // 3) X[q,s] = (KT[b] @ E[b]^T) / RS[b][s]; fused max over s -> XMAX
    hgemm<4><<<dim3(SS / 128, QDIM / 64, BB), 128, SMEM>>>(
        KTh, EH, nullptr, nullptr, nullptr, RS, XMAX,
        SS, SS, SS, SS, 1.0f, strKT, strSC, 0);

    // 4) out = relu(xmax @ W3^T + b3)
    final_head<<<BB, 256>>>(W3, b3, out);
}

// round 12
// speedup vs baseline: 1.2438x; 1.2438x over previous
#include <cuda_runtime.h>
#include <cuda_fp16.h>
#include <cstdint>

#define BB  32
#define SS  2048
#define DD  768
#define QDIM 256
#define ODIM 1024
#define STAGES 4
#define PITCH 40                     // halves per smem row (80B)
#define AROWS 128
#define BROWS 64
#define STGB  ((AROWS + BROWS) * PITCH * 2)   // 15360 bytes per stage

// -------- scratch (allocation-free: __device__ globals) --------
__device__ __half g_dataH[(size_t)BB * SS * DD];
__device__ __half g_W12h[2 * QDIM * DD];           // [W1; W2]
__device__ float  g_B12[2 * QDIM];                 // [b1; b2]
__device__ __half g_QKh[(size_t)BB * SS * 2 * QDIM]; // per row: Q[0:256] K[256:512]
__device__ __half g_KTh[(size_t)BB * QDIM * SS];   // K transposed [b][q][s]
__device__ __half g_EH [(size_t)BB * SS * SS];     // exp(scores) fp16 (256 MB)
__device__ float  g_RS [BB * SS];                  // row sums of exp
__device__ float  g_XMAX[BB * QDIM];               // fused maxpool result

__device__ __forceinline__ uint32_t smem_u32(const void* p) {
    uint32_t a;
    asm("{ .reg .u64 t; cvta.to.shared.u64 t, %1; cvt.u32.u64 %0, t; }" : "=r"(a) : "l"(p));
    return a;
}
__device__ __forceinline__ void cp16(uint32_t dst, const void* src) {
    asm volatile("cp.async.cg.shared.global [%0], [%1], 16;" :: "r"(dst), "l"(src));
}
#define CP_COMMIT() asm volatile("cp.async.commit_group;" ::: "memory")
#define CP_WAIT(n)  asm volatile("cp.async.wait_group %0;" :: "n"(n) : "memory")

__device__ __forceinline__ void ldsm4(uint32_t& r0, uint32_t& r1, uint32_t& r2,
                                      uint32_t& r3, uint32_t addr) {
    asm volatile("ldmatrix.sync.aligned.m8n8.x4.shared.b16 {%0,%1,%2,%3}, [%4];"
                 : "=r"(r0), "=r"(r1), "=r"(r2), "=r"(r3) : "r"(addr));
}

__device__ __forceinline__ void mma16(float* d, const uint32_t* a, const uint32_t* b) {
    asm volatile(
        "mma.sync.aligned.m16n8k16.row.col.f32.f16.f16.f32 "
        "{%0,%1,%2,%3}, {%4,%5,%6,%7}, {%8,%9}, {%0,%1,%2,%3};"
        : "+f"(d[0]), "+f"(d[1]), "+f"(d[2]), "+f"(d[3])
        : "r"(a[0]), "r"(a[1]), "r"(a[2]), "r"(a[3]), "r"(b[0]), "r"(b[1]));
}

// exact, order-independent float atomic max (init must be -inf)
__device__ __forceinline__ void atomicMaxF(float* a, float v) {
    if (v >= 0.f) atomicMax((int*)a, __float_as_int(v));
    else          atomicMin((unsigned int*)a, __float_as_uint(v));
}

// ============================================================================
// fp16 NT GEMM, cp.async 4-stage pipeline + ldmatrix fragments.
// CTA tile 128x64, k-chunk 32, 256 threads (8 warps 4m x 2n), warp tile 32x32.
// acc = 32 regs/thread -> 3 CTAs/SM (24 warps/SM) for latency hiding.
// A [M,K], B [N,K] fp16 row-major.
//   EPI=2: C fp16 + bias; if bn>=256 ALSO CT fp16 transposed per-batch
//          [QDIM][SS] at q = n-256 (merged QK projection)
//   EPI=3: C fp16 = exp(acc*scale); per-row sums atomically added to aux[b*SS+m]
//   EPI=4: no C store; X[m,n] = acc / aux[b*SS+n]; row-max over n fused:
//          atomicMaxF into xmax[b*QDIM+m]
// Smem rows padded to 40 halves (80B): conflict-free ldmatrix.
// Requires M%128==0, N%64==0, kdim%32==0.
// ============================================================================
template <int EPI>
__global__ __launch_bounds__(256, 3) void hgemm(
    const __half* __restrict__ A, const __half* __restrict__ B,
    const float* __restrict__ bias, void* __restrict__ Cv,
    __half* __restrict__ CT, float* __restrict__ aux, float* __restrict__ xmax,
    int lda, int ldb, int ldc, int kdim, float scale,
    size_t sA, size_t sB, size_t sC)
{
    extern __shared__ __half sm[];
    A += (size_t)blockIdx.z * sA;
    B += (size_t)blockIdx.z * sB;
    const int bm = blockIdx.y * 128;
    const int bn = blockIdx.x * 64;

    const int tid = threadIdx.x;
    const int lane = tid & 31, wid = tid >> 5;
    const int wm = wid & 3, wn = wid >> 2;      // warp 32m x 32n
    const int qd = lane >> 2, cc = lane & 3;

    // loaders
    const int arow = tid >> 1;                  // 0..127
    const int aseg = (tid & 1) * 16;            // halves
    const int brow = tid >> 2;                  // 0..63
    const int bseg = (tid & 3) * 8;             // halves
    const __half* pa = A + (size_t)(bm + arow) * lda + aseg;
    const __half* pb = B + (size_t)(bn + brow) * ldb + bseg;
    const uint32_t smb = smem_u32(sm);
    const uint32_t dA = smb + (uint32_t)(arow * PITCH + aseg) * 2;
    const uint32_t dB = smb + (uint32_t)((AROWS + brow) * PITCH + bseg) * 2;

    // ldmatrix per-lane offsets (relative to stage base, ks=0)
    uint32_t aoff[2], boff;
#pragma unroll
    for (int mt = 0; mt < 2; mt++)
        aoff[mt] = (uint32_t)(((wm * 32 + mt * 16 + (lane & 7) + (lane & 8)) * PITCH
                               + ((lane >> 4) * 8)) * 2);
    boff = (uint32_t)(((AROWS + wn * 32 + (lane & 15)
                        + ((lane >> 4) * 16)) * PITCH) * 2);
    // boff covers two n-tiles of 16 via x4: lanes 0-15 -> rows n..n+15 (k0),
    // lanes 16-31 -> rows n+16..n+31 (k0); we instead use the R10 mapping:
    boff = (uint32_t)(((AROWS + wn * 32 + (lane & 7) + ((lane >> 4) * 8)) * PITCH
                       + (lane & 8)) * 2);

    float acc[2][4][4];
#pragma unroll
    for (int i = 0; i < 2; i++)
#pragma unroll
        for (int j = 0; j < 4; j++)
#pragma unroll
            for (int r = 0; r < 4; r++) acc[i][j][r] = 0.f;

    const int nc = kdim >> 5;

    // prologue: stages 0..STAGES-2
#pragma unroll
    for (int s = 0; s < STAGES - 1; s++) {
        if (s < nc) {
            const size_t k0 = (size_t)s * 32;
            cp16(dA + s * STGB,      pa + k0);
            cp16(dA + s * STGB + 16, pa + k0 + 8);
            cp16(dB + s * STGB,      pb + k0);
        }
        CP_COMMIT();
    }

    for (int ch = 0; ch < nc; ch++) {
        CP_WAIT(STAGES - 2);
        __syncthreads();   // stage ch ready; everyone done reading stage ch-1

        // refill the stage freed by chunk ch-1
        {
            const int nxt = ch + STAGES - 1;
            if (nxt < nc) {
                const int st = nxt & (STAGES - 1);
                const size_t k0 = (size_t)nxt * 32;
                cp16(dA + st * STGB,      pa + k0);
                cp16(dA + st * STGB + 16, pa + k0 + 8);
                cp16(dB + st * STGB,      pb + k0);
            }
            CP_COMMIT();
        }

        const uint32_t sa = smb + (uint32_t)(ch & (STAGES - 1)) * STGB;
#pragma unroll
        for (int ks = 0; ks < 2; ks++) {
            uint32_t af[2][4], bf[2][2];
#pragma unroll
            for (int mt = 0; mt < 2; mt++)
                ldsm4(af[mt][0], af[mt][1], af[mt][2], af[mt][3],
                      sa + aoff[mt] + ks * 32);
            // one x4 B-ldsm yields two n-tiles (n, n+8) with both k halves
            ldsm4(bf[0][0], bf[0][1], bf[1][0], bf[1][1], sa + boff + ks * 32);
            // second pair of n-tiles (n+16, n+24)
            uint32_t bf2[2][2];
            ldsm4(bf2[0][0], bf2[0][1], bf2[1][0], bf2[1][1],
                  sa + boff + 16 * PITCH * 2 + ks * 32);
#pragma unroll
            for (int mt = 0; mt < 2; mt++) {
                mma16(acc[mt][0], af[mt], bf[0]);
                mma16(acc[mt][1], af[mt], bf[1]);
                mma16(acc[mt][2], af[mt], bf2[0]);
                mma16(acc[mt][3], af[mt], bf2[1]);
            }
        }
    }

    // ---- epilogue ----
    float inv[4][2];
    if (EPI == 4) {
#pragma unroll
        for (int nt = 0; nt < 4; nt++) {
            const int n0 = bn + wn * 32 + nt * 8 + cc * 2;
            inv[nt][0] = 1.0f / __ldg(&aux[blockIdx.z * SS + n0]);
            inv[nt][1] = 1.0f / __ldg(&aux[blockIdx.z * SS + n0 + 1]);
        }
    }
    float* srs = (float*)sm;   // EPI==3: per-CTA row sums (128 floats)
    if (EPI == 3) {
        __syncthreads();       // all warps done reading pipeline smem
        if (tid < 128) srs[tid] = 0.f;
        __syncthreads();
    }

#pragma unroll
    for (int mt = 0; mt < 2; mt++) {
        const int m0 = bm + wm * 32 + mt * 16 + qd;
        float rs0 = 0.f, rs1 = 0.f;               // EPI==3 row sums
        float mx0 = -INFINITY, mx1 = -INFINITY;   // EPI==4 row maxes
#pragma unroll
        for (int nt = 0; nt < 4; nt++) {
            const int n0 = bn + wn * 32 + nt * 8 + cc * 2;
            float c0 = acc[mt][nt][0] * scale;
            float c1 = acc[mt][nt][1] * scale;
            float c2 = acc[mt][nt][2] * scale;
            float c3 = acc[mt][nt][3] * scale;
            if (EPI == 4) {
                c0 *= inv[nt][0]; c1 *= inv[nt][1];
                c2 *= inv[nt][0]; c3 *= inv[nt][1];
                mx0 = fmaxf(mx0, fmaxf(c0, c1));
                mx1 = fmaxf(mx1, fmaxf(c2, c3));
            } else if (EPI == 3) {
                c0 = __expf(c0); c1 = __expf(c1);
                c2 = __expf(c2); c3 = __expf(c3);
                rs0 += c0 + c1; rs1 += c2 + c3;
                __half2 h0 = __floats2half2_rn(c0, c1);
                __half2 h1 = __floats2half2_rn(c2, c3);
                __half* Ch = (__half*)Cv + (size_t)blockIdx.z * sC;
                *(__half2*)(Ch + (size_t)m0 * ldc + n0)       = h0;
                *(__half2*)(Ch + (size_t)(m0 + 8) * ldc + n0) = h1;
            } else {  // EPI == 2: merged QK projection
                const float bx = bias[n0], by = bias[n0 + 1];
                c0 += bx; c1 += by; c2 += bx; c3 += by;
                __half2 h0 = __floats2half2_rn(c0, c1);
                __half2 h1 = __floats2half2_rn(c2, c3);
                __half* Ch = (__half*)Cv + (size_t)blockIdx.z * sC;
                *(__half2*)(Ch + (size_t)m0 * ldc + n0)       = h0;
                *(__half2*)(Ch + (size_t)(m0 + 8) * ldc + n0) = h1;
                if (bn >= 256) {   // K columns -> transposed copy
                    const int b0 = m0 >> 11, s0 = m0 & (SS - 1);
                    __half* t = CT + ((size_t)b0 * QDIM + (n0 - 256)) * SS + s0;
                    t[0]      = __low2half(h0);
                    t[SS]     = __high2half(h0);
                    t[8]      = __low2half(h1);
                    t[SS + 8] = __high2half(h1);
                }
            }
        }
        if (EPI == 3) {
            rs0 += __shfl_xor_sync(0xffffffffu, rs0, 1);
            rs0 += __shfl_xor_sync(0xffffffffu, rs0, 2);
            rs1 += __shfl_xor_sync(0xffffffffu, rs1, 1);
            rs1 += __shfl_xor_sync(0xffffffffu, rs1, 2);
            if (cc == 0) {
                atomicAdd(&srs[wm * 32 + mt * 16 + qd],     rs0);
                atomicAdd(&srs[wm * 32 + mt * 16 + qd + 8], rs1);
            }
        }
        if (EPI == 4) {
            mx0 = fmaxf(mx0, __shfl_xor_sync(0xffffffffu, mx0, 1));
            mx0 = fmaxf(mx0, __shfl_xor_sync(0xffffffffu, mx0, 2));
            mx1 = fmaxf(mx1, __shfl_xor_sync(0xffffffffu, mx1, 1));
            mx1 = fmaxf(mx1, __shfl_xor_sync(0xffffffffu, mx1, 2));
            if (cc == 0) {
                atomicMaxF(&xmax[blockIdx.z * QDIM + m0],     mx0);
                atomicMaxF(&xmax[blockIdx.z * QDIM + m0 + 8], mx1);
            }
        }
    }
    if (EPI == 3) {
        __syncthreads();
        if (tid < 128) atomicAdd(&aux[blockIdx.z * SS + bm + tid], srs[tid]);
    }
}

// ============================================================================
// init: RS=0 (64 blocks), XMAX=-inf (8 blocks), B12 = [b1;b2] (2 blocks)
// ============================================================================
__global__ __launch_bounds__(256) void init_aux(
    float* __restrict__ rs, float* __restrict__ xmax,
    const float* __restrict__ b1, const float* __restrict__ b2,
    float* __restrict__ b12)
{
    if (blockIdx.x < 64) {
        const int i = blockIdx.x * 1024 + threadIdx.x * 4;
        *(float4*)(rs + i) = make_float4(0.f, 0.f, 0.f, 0.f);
    } else if (blockIdx.x < 72) {
        const int i = (blockIdx.x - 64) * 1024 + threadIdx.x * 4;
        const float ninf = -INFINITY;
        *(float4*)(xmax + i) = make_float4(ninf, ninf, ninf, ninf);
    } else if (blockIdx.x == 72) {
        b12[threadIdx.x] = b1[threadIdx.x];
    } else {
        b12[256 + threadIdx.x] = b2[threadIdx.x];
    }
}

// ============================================================================
// fp32 -> fp16 conversion (n % 8 == 0)
// ============================================================================
__global__ __launch_bounds__(256) void f2h_kernel(
    const float* __restrict__ s, __half* __restrict__ d, size_t n)
{
    const size_t i = ((size_t)blockIdx.x * 256 + threadIdx.x) * 8;
    if (i + 8 <= n) {
        float4 a = *(const float4*)(s + i);
        float4 b = *(const float4*)(s + i + 4);
        uint4 o;
        __half2 h;
        h = __floats2half2_rn(a.x, a.y); o.x = *(uint32_t*)&h;
        h = __floats2half2_rn(a.z, a.w); o.y = *(uint32_t*)&h;
        h = __floats2half2_rn(b.x, b.y); o.z = *(uint32_t*)&h;
        h = __floats2half2_rn(b.z, b.w); o.w = *(uint32_t*)&h;
        *(uint4*)(d + i) = o;
    }
}

// ============================================================================
__global__ __launch_bounds__(256) void final_head(
    const float* __restrict__ W3, const float* __restrict__ b3,
    float* __restrict__ out)
{
    const int b = blockIdx.x;
    const int tid = threadIdx.x;
    __shared__ float xs[QDIM];
    xs[tid] = g_XMAX[b * QDIM + tid];
    __syncthreads();

#pragma unroll
    for (int kk = 0; kk < 4; kk++) {
        const int o = tid + kk * 256;
        const float4* w = (const float4*)(W3 + (size_t)o * QDIM);
        float acc = 0.f;
#pragma unroll
        for (int qq = 0; qq < QDIM / 4; qq++) {
            float4 wv = w[qq];
            acc += wv.x * xs[qq * 4 + 0] + wv.y * xs[qq * 4 + 1]
                 + wv.z * xs[qq * 4 + 2] + wv.w * xs[qq * 4 + 3];
        }
        out[(size_t)b * ODIM + o] = fmaxf(acc + b3[o], 0.f);
    }
}

// ============================================================================
extern "C" void kernel_launch(void* const* d_in, const int* in_sizes, int n_in,
                              void* d_out, int out_size)
{
    const float* data = (const float*)d_in[0];
    /* d_in[1] = seq_len: unused by the reference */
    const float* W1 = (const float*)d_in[2];
    const float* b1 = (const float*)d_in[3];
    const float* W2 = (const float*)d_in[4];
    const float* b2 = (const float*)d_in[5];
    const float* W3 = (const float*)d_in[6];
    const float* b3 = (const float*)d_in[7];
    float* out = (float*)d_out;

    __half *dataH, *W12h, *QKh, *KTh, *EH;
    float *B12, *RS, *XMAX;
    cudaGetSymbolAddress((void**)&dataH, g_dataH);
    cudaGetSymbolAddress((void**)&W12h, g_W12h);
    cudaGetSymbolAddress((void**)&B12,  g_B12);
    cudaGetSymbolAddress((void**)&QKh,  g_QKh);
    cudaGetSymbolAddress((void**)&KTh,  g_KTh);
    cudaGetSymbolAddress((void**)&EH,   g_EH);
    cudaGetSymbolAddress((void**)&RS,   g_RS);
    cudaGetSymbolAddress((void**)&XMAX, g_XMAX);

    const int SMEM = STAGES * STGB;   // 61440 B
    cudaFuncSetAttribute(hgemm<2>, cudaFuncAttributeMaxDynamicSharedMemorySize, SMEM);
    cudaFuncSetAttribute(hgemm<3>, cudaFuncAttributeMaxDynamicSharedMemorySize, SMEM);
    cudaFuncSetAttribute(hgemm<4>, cudaFuncAttributeMaxDynamicSharedMemorySize, SMEM);

    const size_t strQK = (size_t)SS * 2 * QDIM;   // per-batch stride in QKh
    const size_t strKT = (size_t)QDIM * SS;
    const size_t strSC = (size_t)SS * SS;
    const float  inv_sqrt_qd = 1.0f / 16.0f;

    // 0) convert inputs to fp16; init RS=0, XMAX=-inf, B12=[b1;b2]
    const size_t nd = (size_t)BB * SS * DD;
    f2h_kernel<<<(unsigned)(nd / (256 * 8)), 256>>>(data, dataH, nd);
    f2h_kernel<<<(QDIM * DD) / (256 * 8), 256>>>(W1, W12h, QDIM * DD);
    f2h_kernel<<<(QDIM * DD) / (256 * 8), 256>>>(W2, W12h + QDIM * DD, QDIM * DD);
    init_aux<<<74, 256>>>(RS, XMAX, b1, b2, B12);

    // 1) QK = data @ [W1;W2]^T + [b1;b2] -> fp16 [BS][512]; K part also -> KTh
    hgemm<2><<<dim3(512 / 64, (BB * SS) / 128, 1), 256, SMEM>>>(
        dataH, W12h, B12, QKh, KTh, nullptr, nullptr,
        DD, DD, 2 * QDIM, DD, 1.0f, 0, 0, 0);

    // 2) E[b] = exp((K[b] @ Q[b]^T) / 16) -> fp16, rowsums into RS
    hgemm<3><<<dim3(SS / 64, SS / 128, BB), 256, SMEM>>>(
        QKh + 256, QKh, nullptr, EH, nullptr, RS, nullptr,
        2 * QDIM, 2 * QDIM, SS, QDIM, inv_sqrt_qd, strQK, strQK, strSC);

    // 3) X[q,s] = (KT[b] @ E[b]^T) / RS[b][s]; fused max over s -> XMAX
    hgemm<4><<<dim3(SS / 64, QDIM / 128, BB), 256, SMEM>>>(
        KTh, EH, nullptr, nullptr, nullptr, RS, XMAX,
        SS, SS, SS, SS, 1.0f, strKT, strSC, 0);

    // 4) out = relu(xmax @ W3^T + b3)
    final_head<<<BB, 256>>>(W3, b3, out);
}

// round 13
// speedup vs baseline: 1.4196x; 1.1413x over previous
#include <cuda_runtime.h>
#include <cuda_fp16.h>
#include <cstdint>

#define BB  32
#define SS  2048
#define DD  768
#define QDIM 256
#define ODIM 1024
#define STAGES 4

// -------- scratch (allocation-free: __device__ globals) --------
__device__ __half g_dataH[(size_t)BB * SS * DD];
__device__ __half g_W12h[2 * QDIM * DD];           // [W1; W2] rows 0-255 / 256-511
__device__ float  g_B12[2 * QDIM];                 // [b1; b2]
__device__ __half g_QKh[(size_t)BB * SS * 2 * QDIM]; // per row: Q[0:256] K[256:512]
__device__ __half g_KTh[(size_t)BB * QDIM * SS];   // K transposed [b][q][s]
__device__ __half g_EH [(size_t)BB * SS * SS];     // exp(scores) fp16 (256 MB)
__device__ float  g_RS [BB * SS];                  // row sums of exp
__device__ float  g_XMAX[BB * QDIM];               // fused maxpool result

__device__ __forceinline__ uint32_t smem_u32(const void* p) {
    uint32_t a;
    asm("{ .reg .u64 t; cvta.to.shared.u64 t, %1; cvt.u32.u64 %0, t; }" : "=r"(a) : "l"(p));
    return a;
}
__device__ __forceinline__ void cp16(uint32_t dst, const void* src) {
    asm volatile("cp.async.cg.shared.global [%0], [%1], 16;" :: "r"(dst), "l"(src));
}
#define CP_COMMIT() asm volatile("cp.async.commit_group;" ::: "memory")
#define CP_WAIT(n)  asm volatile("cp.async.wait_group %0;" :: "n"(n) : "memory")

__device__ __forceinline__ void ldsm4(uint32_t& r0, uint32_t& r1, uint32_t& r2,
                                      uint32_t& r3, uint32_t addr) {
    asm volatile("ldmatrix.sync.aligned.m8n8.x4.shared.b16 {%0,%1,%2,%3}, [%4];"
                 : "=r"(r0), "=r"(r1), "=r"(r2), "=r"(r3) : "r"(addr));
}

// NOTE: intentionally NOT volatile — pure register op; lets ptxas interleave
// HMMA issue with subsequent ldmatrix to hide LDS latency.
__device__ __forceinline__ void mma16(float* d, const uint32_t* a, const uint32_t* b) {
    asm("mma.sync.aligned.m16n8k16.row.col.f32.f16.f16.f32 "
        "{%0,%1,%2,%3}, {%4,%5,%6,%7}, {%8,%9}, {%0,%1,%2,%3};"
        : "+f"(d[0]), "+f"(d[1]), "+f"(d[2]), "+f"(d[3])
        : "r"(a[0]), "r"(a[1]), "r"(a[2]), "r"(a[3]), "r"(b[0]), "r"(b[1]));
}

// exact, order-independent float atomic max (init must be -inf)
__device__ __forceinline__ void atomicMaxF(float* a, float v) {
    if (v >= 0.f) atomicMax((int*)a, __float_as_int(v));
    else          atomicMin((unsigned int*)a, __float_as_uint(v));
}

// ============================================================================
// fp16 NT GEMM, cp.async 4-stage pipeline + ldmatrix fragment loads.
// CTA 128x128, k-chunk 32, 256 thr (8 warps 2x4), warp tile 64x32.
// A [M,K], B [N,K] fp16 row-major.
//   EPI=2: C fp16 + bias; if bn>=256 ALSO CT fp16 transposed per-batch
//          [QDIM][SS] at q = n-256 (merged QK projection)
//   EPI=3: C fp16 = exp(acc*scale); per-row sums atomically added to aux[b*SS+m]
//   EPI=4: no C store; X[m,n] = acc / aux[b*SS+n]; row-max over n fused:
//          atomicMaxF into xmax[b*QDIM+m]
// Smem rows padded to 40 halves (80B): conflict-free ldmatrix.
// Requires M%128==0, N%128==0, kdim%32==0.
// ============================================================================
template <int EPI>
__global__ __launch_bounds__(256, 2) void hgemm(
    const __half* __restrict__ A, const __half* __restrict__ B,
    const float* __restrict__ bias, void* __restrict__ Cv,
    __half* __restrict__ CT, float* __restrict__ aux, float* __restrict__ xmax,
    int lda, int ldb, int ldc, int kdim, float scale,
    size_t sA, size_t sB, size_t sC)
{
    extern __shared__ __half sm[];
    A += (size_t)blockIdx.z * sA;
    B += (size_t)blockIdx.z * sB;
    const int bm = blockIdx.y * 128;
    const int bn = blockIdx.x * 128;

    const int tid = threadIdx.x;
    const int lane = tid & 31, wid = tid >> 5;
    const int wm = wid & 1, wn = wid >> 1;      // warp 64m x 32n
    const int qd = lane >> 2, cc = lane & 3;

    // loader: thread covers row = tid>>1, halves [seg, seg+16)
    const int lrow = tid >> 1;
    const int lseg = (tid & 1) * 16;
    const __half* pa = A + (size_t)(bm + lrow) * lda + lseg;
    const __half* pb = B + (size_t)(bn + lrow) * ldb + lseg;
    const uint32_t smb = smem_u32(sm);
    const uint32_t dA = smb + (uint32_t)(lrow * 40 + lseg) * 2;
    const uint32_t dB = dA + 5120 * 2;
    const uint32_t STG = 10240 * 2;             // bytes per stage (A+B)

    // ldmatrix per-lane offsets (relative to stage base, ks=0)
    uint32_t aoff[4], boff[2];
#pragma unroll
    for (int mt = 0; mt < 4; mt++)
        aoff[mt] = (uint32_t)(((wm * 64 + mt * 16 + (lane & 7) + (lane & 8)) * 40
                               + ((lane >> 4) * 8)) * 2);
#pragma unroll
    for (int np = 0; np < 2; np++)
        boff[np] = (uint32_t)(5120 * 2
                   + ((wn * 32 + np * 16 + (lane & 7) + ((lane >> 4) * 8)) * 40
                      + (lane & 8)) * 2);

    float acc[4][4][4];
#pragma unroll
    for (int i = 0; i < 4; i++)
#pragma unroll
        for (int j = 0; j < 4; j++)
#pragma unroll
            for (int r = 0; r < 4; r++) acc[i][j][r] = 0.f;

    const int nc = kdim >> 5;

    // prologue: stages 0..STAGES-2
#pragma unroll
    for (int s = 0; s < STAGES - 1; s++) {
        if (s < nc) {
            const size_t k0 = (size_t)s * 32;
            const uint32_t da = dA + s * STG, db = dB + s * STG;
            cp16(da,      pa + k0);
            cp16(da + 16, pa + k0 + 8);
            cp16(db,      pb + k0);
            cp16(db + 16, pb + k0 + 8);
        }
        CP_COMMIT();
    }

    for (int ch = 0; ch < nc; ch++) {
        CP_WAIT(STAGES - 2);
        __syncthreads();   // stage ch ready; everyone done reading stage ch-1

        // refill the stage freed by chunk ch-1
        {
            const int nxt = ch + STAGES - 1;
            if (nxt < nc) {
                const int st = nxt & (STAGES - 1);
                const size_t k0 = (size_t)nxt * 32;
                const uint32_t da = dA + st * STG, db = dB + st * STG;
                cp16(da,      pa + k0);
                cp16(da + 16, pa + k0 + 8);
                cp16(db,      pb + k0);
                cp16(db + 16, pb + k0 + 8);
            }
            CP_COMMIT();
        }

        const uint32_t sa = smb + (uint32_t)(ch & (STAGES - 1)) * STG;
#pragma unroll
        for (int ks = 0; ks < 2; ks++) {
            uint32_t af[4][4], bf[4][2];
#pragma unroll
            for (int mt = 0; mt < 4; mt++)
                ldsm4(af[mt][0], af[mt][1], af[mt][2], af[mt][3],
                      sa + aoff[mt] + ks * 32);
#pragma unroll
            for (int np = 0; np < 2; np++)
                ldsm4(bf[2 * np][0], bf[2 * np][1], bf[2 * np + 1][0],
                      bf[2 * np + 1][1], sa + boff[np] + ks * 32);
#pragma unroll
            for (int mt = 0; mt < 4; mt++)
#pragma unroll
                for (int nt = 0; nt < 4; nt++)
                    mma16(acc[mt][nt], af[mt], bf[nt]);
        }
    }

    // ---- epilogue ----
    float inv[4][2];
    if (EPI == 4) {
#pragma unroll
        for (int nt = 0; nt < 4; nt++) {
            const int n0 = bn + wn * 32 + nt * 8 + cc * 2;
            inv[nt][0] = 1.0f / __ldg(&aux[blockIdx.z * SS + n0]);
            inv[nt][1] = 1.0f / __ldg(&aux[blockIdx.z * SS + n0 + 1]);
        }
    }
    float* srs = (float*)sm;   // EPI==3: per-CTA row sums (128 floats)
    if (EPI == 3) {
        __syncthreads();       // all warps done reading pipeline smem
        if (tid < 128) srs[tid] = 0.f;
        __syncthreads();
    }

#pragma unroll
    for (int mt = 0; mt < 4; mt++) {
        const int m0 = bm + wm * 64 + mt * 16 + qd;
        float rs0 = 0.f, rs1 = 0.f;               // EPI==3 row sums
        float mx0 = -INFINITY, mx1 = -INFINITY;   // EPI==4 row maxes
#pragma unroll
        for (int nt = 0; nt < 4; nt++) {
            const int n0 = bn + wn * 32 + nt * 8 + cc * 2;
            float c0 = acc[mt][nt][0] * scale;
            float c1 = acc[mt][nt][1] * scale;
            float c2 = acc[mt][nt][2] * scale;
            float c3 = acc[mt][nt][3] * scale;
            if (EPI == 4) {
                c0 *= inv[nt][0]; c1 *= inv[nt][1];
                c2 *= inv[nt][0]; c3 *= inv[nt][1];
                mx0 = fmaxf(mx0, fmaxf(c0, c1));
                mx1 = fmaxf(mx1, fmaxf(c2, c3));
            } else if (EPI == 3) {
                c0 = __expf(c0); c1 = __expf(c1);
                c2 = __expf(c2); c3 = __expf(c3);
                rs0 += c0 + c1; rs1 += c2 + c3;
                __half2 h0 = __floats2half2_rn(c0, c1);
                __half2 h1 = __floats2half2_rn(c2, c3);
                __half* Ch = (__half*)Cv + (size_t)blockIdx.z * sC;
                *(__half2*)(Ch + (size_t)m0 * ldc + n0)       = h0;
                *(__half2*)(Ch + (size_t)(m0 + 8) * ldc + n0) = h1;
            } else {  // EPI == 2: merged QK projection
                const float bx = bias[n0], by = bias[n0 + 1];
                c0 += bx; c1 += by; c2 += bx; c3 += by;
                __half2 h0 = __floats2half2_rn(c0, c1);
                __half2 h1 = __floats2half2_rn(c2, c3);
                __half* Ch = (__half*)Cv + (size_t)blockIdx.z * sC;
                *(__half2*)(Ch + (size_t)m0 * ldc + n0)       = h0;
                *(__half2*)(Ch + (size_t)(m0 + 8) * ldc + n0) = h1;
                if (bn >= 256) {   // K columns -> transposed copy
                    const int b0 = m0 >> 11, s0 = m0 & (SS - 1);
                    __half* t = CT + ((size_t)b0 * QDIM + (n0 - 256)) * SS + s0;
                    t[0]      = __low2half(h0);
                    t[SS]     = __high2half(h0);
                    t[8]      = __low2half(h1);
                    t[SS + 8] = __high2half(h1);
                }
            }
        }
        if (EPI == 3) {
            rs0 += __shfl_xor_sync(0xffffffffu, rs0, 1);
            rs0 += __shfl_xor_sync(0xffffffffu, rs0, 2);
            rs1 += __shfl_xor_sync(0xffffffffu, rs1, 1);
            rs1 += __shfl_xor_sync(0xffffffffu, rs1, 2);
            if (cc == 0) {
                atomicAdd(&srs[wm * 64 + mt * 16 + qd],     rs0);
                atomicAdd(&srs[wm * 64 + mt * 16 + qd + 8], rs1);
            }
        }
        if (EPI == 4) {
            mx0 = fmaxf(mx0, __shfl_xor_sync(0xffffffffu, mx0, 1));
            mx0 = fmaxf(mx0, __shfl_xor_sync(0xffffffffu, mx0, 2));
            mx1 = fmaxf(mx1, __shfl_xor_sync(0xffffffffu, mx1, 1));
            mx1 = fmaxf(mx1, __shfl_xor_sync(0xffffffffu, mx1, 2));
            if (cc == 0) {
                atomicMaxF(&xmax[blockIdx.z * QDIM + m0],     mx0);
                atomicMaxF(&xmax[blockIdx.z * QDIM + m0 + 8], mx1);
            }
        }
    }
    if (EPI == 3) {
        __syncthreads();
        if (tid < 128) atomicAdd(&aux[blockIdx.z * SS + bm + tid], srs[tid]);
    }
}

// ============================================================================
// init: RS=0 (64 blocks), XMAX=-inf (8 blocks), B12 = [b1;b2] (2 blocks)
// ============================================================================
__global__ __launch_bounds__(256) void init_aux(
    float* __restrict__ rs, float* __restrict__ xmax,
    const float* __restrict__ b1, const float* __restrict__ b2,
    float* __restrict__ b12)
{
    if (blockIdx.x < 64) {
        const int i = blockIdx.x * 1024 + threadIdx.x * 4;
        *(float4*)(rs + i) = make_float4(0.f, 0.f, 0.f, 0.f);
    } else if (blockIdx.x < 72) {
        const int i = (blockIdx.x - 64) * 1024 + threadIdx.x * 4;
        const float ninf = -INFINITY;
        *(float4*)(xmax + i) = make_float4(ninf, ninf, ninf, ninf);
    } else if (blockIdx.x == 72) {
        b12[threadIdx.x] = b1[threadIdx.x];
    } else {
        b12[256 + threadIdx.x] = b2[threadIdx.x];
    }
}

// ============================================================================
// fp32 -> fp16 conversion (n % 8 == 0)
// ============================================================================
__global__ __launch_bounds__(256) void f2h_kernel(
    const float* __restrict__ s, __half* __restrict__ d, size_t n)
{
    const size_t i = ((size_t)blockIdx.x * 256 + threadIdx.x) * 8;
    if (i + 8 <= n) {
        float4 a = *(const float4*)(s + i);
        float4 b = *(const float4*)(s + i + 4);
        uint4 o;
        __half2 h;
        h = __floats2half2_rn(a.x, a.y); o.x = *(uint32_t*)&h;
        h = __floats2half2_rn(a.z, a.w); o.y = *(uint32_t*)&h;
        h = __floats2half2_rn(b.x, b.y); o.z = *(uint32_t*)&h;
        h = __floats2half2_rn(b.z, b.w); o.w = *(uint32_t*)&h;
        *(uint4*)(d + i) = o;
    }
}

// ============================================================================
__global__ __launch_bounds__(256) void final_head(
    const float* __restrict__ W3, const float* __restrict__ b3,
    float* __restrict__ out)
{
    const int b = blockIdx.x;
    const int tid = threadIdx.x;
    __shared__ float xs[QDIM];
    xs[tid] = g_XMAX[b * QDIM + tid];
    __syncthreads();

#pragma unroll
    for (int kk = 0; kk < 4; kk++) {
        const int o = tid + kk * 256;
        const float4* w = (const float4*)(W3 + (size_t)o * QDIM);
        float acc = 0.f;
#pragma unroll
        for (int qq = 0; qq < QDIM / 4; qq++) {
            float4 wv = w[qq];
            acc += wv.x * xs[qq * 4 + 0] + wv.y * xs[qq * 4 + 1]
                 + wv.z * xs[qq * 4 + 2] + wv.w * xs[qq * 4 + 3];
        }
        out[(size_t)b * ODIM + o] = fmaxf(acc + b3[o], 0.f);
    }
}

// ============================================================================
extern "C" void kernel_launch(void* const* d_in, const int* in_sizes, int n_in,
                              void* d_out, int out_size)
{
    const float* data = (const float*)d_in[0];
    /* d_in[1] = seq_len: unused by the reference */
    const float* W1 = (const float*)d_in[2];
    const float* b1 = (const float*)d_in[3];
    const float* W2 = (const float*)d_in[4];
    const float* b2 = (const float*)d_in[5];
    const float* W3 = (const float*)d_in[6];
    const float* b3 = (const float*)d_in[7];
    float* out = (float*)d_out;

    __half *dataH, *W12h, *QKh, *KTh, *EH;
    float *B12, *RS, *XMAX;
    cudaGetSymbolAddress((void**)&dataH, g_dataH);
    cudaGetSymbolAddress((void**)&W12h, g_W12h);
    cudaGetSymbolAddress((void**)&B12,  g_B12);
    cudaGetSymbolAddress((void**)&QKh,  g_QKh);
    cudaGetSymbolAddress((void**)&KTh,  g_KTh);
    cudaGetSymbolAddress((void**)&EH,   g_EH);
    cudaGetSymbolAddress((void**)&RS,   g_RS);
    cudaGetSymbolAddress((void**)&XMAX, g_XMAX);

    const int SMEM = STAGES * 10240 * 2;   // 81920 B
    cudaFuncSetAttribute(hgemm<2>, cudaFuncAttributeMaxDynamicSharedMemorySize, SMEM);
    cudaFuncSetAttribute(hgemm<3>, cudaFuncAttributeMaxDynamicSharedMemorySize, SMEM);
    cudaFuncSetAttribute(hgemm<4>, cudaFuncAttributeMaxDynamicSharedMemorySize, SMEM);

    const size_t strQK = (size_t)SS * 2 * QDIM;   // per-batch stride in QKh
    const size_t strKT = (size_t)QDIM * SS;
    const size_t strSC = (size_t)SS * SS;
    const float  inv_sqrt_qd = 1.0f / 16.0f;

    // 0) convert inputs to fp16; init RS=0, XMAX=-inf, B12=[b1;b2]
    const size_t nd = (size_t)BB * SS * DD;
    f2h_kernel<<<(unsigned)(nd / (256 * 8)), 256>>>(data, dataH, nd);
    f2h_kernel<<<(QDIM * DD) / (256 * 8), 256>>>(W1, W12h, QDIM * DD);
    f2h_kernel<<<(QDIM * DD) / (256 * 8), 256>>>(W2, W12h + QDIM * DD, QDIM * DD);
    init_aux<<<74, 256>>>(RS, XMAX, b1, b2, B12);

    // 1) QK = data @ [W1;W2]^T + [b1;b2] -> fp16 [BS][512]; K part also -> KTh
    hgemm<2><<<dim3(512 / 128, (BB * SS) / 128, 1), 256, SMEM>>>(
        dataH, W12h, B12, QKh, KTh, nullptr, nullptr,
        DD, DD, 2 * QDIM, DD, 1.0f, 0, 0, 0);

    // 2) E[b] = exp((K[b] @ Q[b]^T) / 16) -> fp16, rowsums into RS
    hgemm<3><<<dim3(SS / 128, SS / 128, BB), 256, SMEM>>>(
        QKh + 256, QKh, nullptr, EH, nullptr, RS, nullptr,
        2 * QDIM, 2 * QDIM, SS, QDIM, inv_sqrt_qd, strQK, strQK, strSC);

    // 3) X[q,s] = (KT[b] @ E[b]^T) / RS[b][s]; fused max over s -> XMAX
    hgemm<4><<<dim3(SS / 128, QDIM / 128, BB), 256, SMEM>>>(
        KTh, EH, nullptr, nullptr, nullptr, RS, XMAX,
        SS, SS, SS, SS, 1.0f, strKT, strSC, 0);

    // 4) out = relu(xmax @ W3^T + b3)
    final_head<<<BB, 256>>>(W3, b3, out);
}

// round 14
// speedup vs baseline: 1.4270x; 1.0052x over previous
#include <cuda_runtime.h>
#include <cuda_fp16.h>
#include <cstdint>

#define BB  32
#define SS  2048
#define DD  768
#define QDIM 256
#define ODIM 1024
#define STAGES 4

// -------- scratch (allocation-free: __device__ globals) --------
__device__ __half g_dataH[(size_t)BB * SS * DD];
__device__ __half g_W12h[2 * QDIM * DD];           // [W1; W2] rows 0-255 / 256-511
__device__ float  g_B12[2 * QDIM];                 // [b1; b2]
__device__ __half g_QKh[(size_t)BB * SS * 2 * QDIM]; // per row: Q[0:256] K[256:512]
__device__ __half g_KTh[(size_t)BB * QDIM * SS];   // K transposed [b][q][s]
__device__ __half g_EH [(size_t)BB * SS * SS];     // exp(scores) fp16 (256 MB)
__device__ float  g_RS [BB * SS];                  // row sums of exp
__device__ float  g_XMAX[BB * QDIM];               // fused maxpool result

__device__ __forceinline__ uint32_t smem_u32(const void* p) {
    uint32_t a;
    asm("{ .reg .u64 t; cvta.to.shared.u64 t, %1; cvt.u32.u64 %0, t; }" : "=r"(a) : "l"(p));
    return a;
}
__device__ __forceinline__ void cp16(uint32_t dst, const void* src) {
    asm volatile("cp.async.cg.shared.global [%0], [%1], 16;" :: "r"(dst), "l"(src));
}
#define CP_COMMIT() asm volatile("cp.async.commit_group;" ::: "memory")
#define CP_WAIT(n)  asm volatile("cp.async.wait_group %0;" :: "n"(n) : "memory")

__device__ __forceinline__ void ldsm4(uint32_t& r0, uint32_t& r1, uint32_t& r2,
                                      uint32_t& r3, uint32_t addr) {
    asm volatile("ldmatrix.sync.aligned.m8n8.x4.shared.b16 {%0,%1,%2,%3}, [%4];"
                 : "=r"(r0), "=r"(r1), "=r"(r2), "=r"(r3) : "r"(addr));
}

__device__ __forceinline__ void mma16(float* d, const uint32_t* a, const uint32_t* b) {
    asm("mma.sync.aligned.m16n8k16.row.col.f32.f16.f16.f32 "
        "{%0,%1,%2,%3}, {%4,%5,%6,%7}, {%8,%9}, {%0,%1,%2,%3};"
        : "+f"(d[0]), "+f"(d[1]), "+f"(d[2]), "+f"(d[3])
        : "r"(a[0]), "r"(a[1]), "r"(a[2]), "r"(a[3]), "r"(b[0]), "r"(b[1]));
}

// two fp16 exponentials (base-2) in one MUFU op
__device__ __forceinline__ uint32_t ex2_h2(float x, float y) {
    __half2 h = __floats2half2_rn(x, y);
    uint32_t r;
    asm("ex2.approx.f16x2 %0, %1;" : "=r"(r) : "r"(*(uint32_t*)&h));
    return r;
}

// exact, order-independent float atomic max (init must be -inf)
__device__ __forceinline__ void atomicMaxF(float* a, float v) {
    if (v >= 0.f) atomicMax((int*)a, __float_as_int(v));
    else          atomicMin((unsigned int*)a, __float_as_uint(v));
}

// ============================================================================
// fp16 NT GEMM, cp.async 4-stage pipeline + ldmatrix fragment loads.
// CTA 128x128, k-chunk 32, 256 thr (8 warps 2x4), warp tile 64x32.
// A [M,K], B [N,K] fp16 row-major.
//   EPI=2: C fp16 + bias; if bn>=256 ALSO CT fp16 transposed per-batch
//          [QDIM][SS] at q = n-256 (merged QK projection)
//   EPI=3: C fp16 = exp2(acc*scale)  (scale carries log2e factor);
//          per-row sums (of the stored fp16 values) atomically added to
//          aux[b*SS+m]
//   EPI=4: no C store; X[m,n] = acc / aux[b*SS+n]; row-max over n fused:
//          atomicMaxF into xmax[b*QDIM+m]
// Smem rows padded to 40 halves (80B): conflict-free ldmatrix.
// Requires M%128==0, N%128==0, kdim%32==0.
// ============================================================================
template <int EPI>
__global__ __launch_bounds__(256, 2) void hgemm(
    const __half* __restrict__ A, const __half* __restrict__ B,
    const float* __restrict__ bias, void* __restrict__ Cv,
    __half* __restrict__ CT, float* __restrict__ aux, float* __restrict__ xmax,
    int lda, int ldb, int ldc, int kdim, float scale,
    size_t sA, size_t sB, size_t sC)
{
    extern __shared__ __half sm[];
    A += (size_t)blockIdx.z * sA;
    B += (size_t)blockIdx.z * sB;
    const int bm = blockIdx.y * 128;
    const int bn = blockIdx.x * 128;

    const int tid = threadIdx.x;
    const int lane = tid & 31, wid = tid >> 5;
    const int wm = wid & 1, wn = wid >> 1;      // warp 64m x 32n
    const int qd = lane >> 2, cc = lane & 3;

    // loader: thread covers row = tid>>1, halves [seg, seg+16)
    const int lrow = tid >> 1;
    const int lseg = (tid & 1) * 16;
    const __half* pa = A + (size_t)(bm + lrow) * lda + lseg;
    const __half* pb = B + (size_t)(bn + lrow) * ldb + lseg;
    const uint32_t smb = smem_u32(sm);
    const uint32_t dA = smb + (uint32_t)(lrow * 40 + lseg) * 2;
    const uint32_t dB = dA + 5120 * 2;
    const uint32_t STG = 10240 * 2;             // bytes per stage (A+B)

    // ldmatrix per-lane offsets (relative to stage base, ks=0)
    uint32_t aoff[4], boff[2];
#pragma unroll
    for (int mt = 0; mt < 4; mt++)
        aoff[mt] = (uint32_t)(((wm * 64 + mt * 16 + (lane & 7) + (lane & 8)) * 40
                               + ((lane >> 4) * 8)) * 2);
#pragma unroll
    for (int np = 0; np < 2; np++)
        boff[np] = (uint32_t)(5120 * 2
                   + ((wn * 32 + np * 16 + (lane & 7) + ((lane >> 4) * 8)) * 40
                      + (lane & 8)) * 2);

    float acc[4][4][4];
#pragma unroll
    for (int i = 0; i < 4; i++)
#pragma unroll
        for (int j = 0; j < 4; j++)
#pragma unroll
            for (int r = 0; r < 4; r++) acc[i][j][r] = 0.f;

    const int nc = kdim >> 5;

    // prologue: stages 0..STAGES-2
#pragma unroll
    for (int s = 0; s < STAGES - 1; s++) {
        if (s < nc) {
            const size_t k0 = (size_t)s * 32;
            const uint32_t da = dA + s * STG, db = dB + s * STG;
            cp16(da,      pa + k0);
            cp16(da + 16, pa + k0 + 8);
            cp16(db,      pb + k0);
            cp16(db + 16, pb + k0 + 8);
        }
        CP_COMMIT();
    }

    for (int ch = 0; ch < nc; ch++) {
        CP_WAIT(STAGES - 2);
        __syncthreads();   // stage ch ready; everyone done reading stage ch-1

        // refill the stage freed by chunk ch-1
        {
            const int nxt = ch + STAGES - 1;
            if (nxt < nc) {
                const int st = nxt & (STAGES - 1);
                const size_t k0 = (size_t)nxt * 32;
                const uint32_t da = dA + st * STG, db = dB + st * STG;
                cp16(da,      pa + k0);
                cp16(da + 16, pa + k0 + 8);
                cp16(db,      pb + k0);
                cp16(db + 16, pb + k0 + 8);
            }
            CP_COMMIT();
        }

        const uint32_t sa = smb + (uint32_t)(ch & (STAGES - 1)) * STG;
#pragma unroll
        for (int ks = 0; ks < 2; ks++) {
            uint32_t af[4][4], bf[4][2];
#pragma unroll
            for (int mt = 0; mt < 4; mt++)
                ldsm4(af[mt][0], af[mt][1], af[mt][2], af[mt][3],
                      sa + aoff[mt] + ks * 32);
#pragma unroll
            for (int np = 0; np < 2; np++)
                ldsm4(bf[2 * np][0], bf[2 * np][1], bf[2 * np + 1][0],
                      bf[2 * np + 1][1], sa + boff[np] + ks * 32);
#pragma unroll
            for (int mt = 0; mt < 4; mt++)
#pragma unroll
                for (int nt = 0; nt < 4; nt++)
                    mma16(acc[mt][nt], af[mt], bf[nt]);
        }
    }

    // ---- epilogue ----
    float inv[4][2];
    if (EPI == 4) {
#pragma unroll
        for (int nt = 0; nt < 4; nt++) {
            const int n0 = bn + wn * 32 + nt * 8 + cc * 2;
            inv[nt][0] = 1.0f / __ldg(&aux[blockIdx.z * SS + n0]);
            inv[nt][1] = 1.0f / __ldg(&aux[blockIdx.z * SS + n0 + 1]);
        }
    }
    float* srs = (float*)sm;   // EPI==3: per-CTA row sums (128 floats)
    if (EPI == 3) {
        __syncthreads();       // all warps done reading pipeline smem
        if (tid < 128) srs[tid] = 0.f;
        __syncthreads();
    }

#pragma unroll
    for (int mt = 0; mt < 4; mt++) {
        const int m0 = bm + wm * 64 + mt * 16 + qd;
        float rs0 = 0.f, rs1 = 0.f;               // EPI==3 row sums
        float mx0 = -INFINITY, mx1 = -INFINITY;   // EPI==4 row maxes
#pragma unroll
        for (int nt = 0; nt < 4; nt++) {
            const int n0 = bn + wn * 32 + nt * 8 + cc * 2;
            float c0 = acc[mt][nt][0] * scale;
            float c1 = acc[mt][nt][1] * scale;
            float c2 = acc[mt][nt][2] * scale;
            float c3 = acc[mt][nt][3] * scale;
            if (EPI == 4) {
                c0 *= inv[nt][0]; c1 *= inv[nt][1];
                c2 *= inv[nt][0]; c3 *= inv[nt][1];
                mx0 = fmaxf(mx0, fmaxf(c0, c1));
                mx1 = fmaxf(mx1, fmaxf(c2, c3));
            } else if (EPI == 3) {
                // E = exp2(score * log2e / 16) computed 2-at-a-time on MUFU
                const uint32_t e0 = ex2_h2(c0, c1);
                const uint32_t e1 = ex2_h2(c2, c3);
                const float2 f0 = __half22float2(*(const __half2*)&e0);
                const float2 f1 = __half22float2(*(const __half2*)&e1);
                rs0 += f0.x + f0.y;
                rs1 += f1.x + f1.y;
                __half* Ch = (__half*)Cv + (size_t)blockIdx.z * sC;
                *(uint32_t*)(Ch + (size_t)m0 * ldc + n0)       = e0;
                *(uint32_t*)(Ch + (size_t)(m0 + 8) * ldc + n0) = e1;
            } else {  // EPI == 2: merged QK projection
                const float bx = bias[n0], by = bias[n0 + 1];
                c0 += bx; c1 += by; c2 += bx; c3 += by;
                __half2 h0 = __floats2half2_rn(c0, c1);
                __half2 h1 = __floats2half2_rn(c2, c3);
                __half* Ch = (__half*)Cv + (size_t)blockIdx.z * sC;
                *(__half2*)(Ch + (size_t)m0 * ldc + n0)       = h0;
                *(__half2*)(Ch + (size_t)(m0 + 8) * ldc + n0) = h1;
                if (bn >= 256) {   // K columns -> transposed copy
                    const int b0 = m0 >> 11, s0 = m0 & (SS - 1);
                    __half* t = CT + ((size_t)b0 * QDIM + (n0 - 256)) * SS + s0;
                    t[0]      = __low2half(h0);
                    t[SS]     = __high2half(h0);
                    t[8]      = __low2half(h1);
                    t[SS + 8] = __high2half(h1);
                }
            }
        }
        if (EPI == 3) {
            rs0 += __shfl_xor_sync(0xffffffffu, rs0, 1);
            rs0 += __shfl_xor_sync(0xffffffffu, rs0, 2);
            rs1 += __shfl_xor_sync(0xffffffffu, rs1, 1);
            rs1 += __shfl_xor_sync(0xffffffffu, rs1, 2);
            if (cc == 0) {
                atomicAdd(&srs[wm * 64 + mt * 16 + qd],     rs0);
                atomicAdd(&srs[wm * 64 + mt * 16 + qd + 8], rs1);
            }
        }
        if (EPI == 4) {
            mx0 = fmaxf(mx0, __shfl_xor_sync(0xffffffffu, mx0, 1));
            mx0 = fmaxf(mx0, __shfl_xor_sync(0xffffffffu, mx0, 2));
            mx1 = fmaxf(mx1, __shfl_xor_sync(0xffffffffu, mx1, 1));
            mx1 = fmaxf(mx1, __shfl_xor_sync(0xffffffffu, mx1, 2));
            if (cc == 0) {
                atomicMaxF(&xmax[blockIdx.z * QDIM + m0],     mx0);
                atomicMaxF(&xmax[blockIdx.z * QDIM + m0 + 8], mx1);
            }
        }
    }
    if (EPI == 3) {
        __syncthreads();
        if (tid < 128) atomicAdd(&aux[blockIdx.z * SS + bm + tid], srs[tid]);
    }
}

// ============================================================================
// init: RS=0 (64 blocks), XMAX=-inf (8 blocks), B12 = [b1;b2] (2 blocks)
// ============================================================================
__global__ __launch_bounds__(256) void init_aux(
    float* __restrict__ rs, float* __restrict__ xmax,
    const float* __restrict__ b1, const float* __restrict__ b2,
    float* __restrict__ b12)
{
    if (blockIdx.x < 64) {
        const int i = blockIdx.x * 1024 + threadIdx.x * 4;
        *(float4*)(rs + i) = make_float4(0.f, 0.f, 0.f, 0.f);
    } else if (blockIdx.x < 72) {
        const int i = (blockIdx.x - 64) * 1024 + threadIdx.x * 4;
        const float ninf = -INFINITY;
        *(float4*)(xmax + i) = make_float4(ninf, ninf, ninf, ninf);
    } else if (blockIdx.x == 72) {
        b12[threadIdx.x] = b1[threadIdx.x];
    } else {
        b12[256 + threadIdx.x] = b2[threadIdx.x];
    }
}

// ============================================================================
// fp32 -> fp16 conversion (n % 8 == 0)
// ============================================================================
__global__ __launch_bounds__(256) void f2h_kernel(
    const float* __restrict__ s, __half* __restrict__ d, size_t n)
{
    const size_t i = ((size_t)blockIdx.x * 256 + threadIdx.x) * 8;
    if (i + 8 <= n) {
        float4 a = *(const float4*)(s + i);
        float4 b = *(const float4*)(s + i + 4);
        uint4 o;
        __half2 h;
        h = __floats2half2_rn(a.x, a.y); o.x = *(uint32_t*)&h;
        h = __floats2half2_rn(a.z, a.w); o.y = *(uint32_t*)&h;
        h = __floats2half2_rn(b.x, b.y); o.z = *(uint32_t*)&h;
        h = __floats2half2_rn(b.z, b.w); o.w = *(uint32_t*)&h;
        *(uint4*)(d + i) = o;
    }
}

// ============================================================================
__global__ __launch_bounds__(256) void final_head(
    const float* __restrict__ W3, const float* __restrict__ b3,
    float* __restrict__ out)
{
    const int b = blockIdx.x;
    const int tid = threadIdx.x;
    __shared__ float xs[QDIM];
    xs[tid] = g_XMAX[b * QDIM + tid];
    __syncthreads();

#pragma unroll
    for (int kk = 0; kk < 4; kk++) {
        const int o = tid + kk * 256;
        const float4* w = (const float4*)(W3 + (size_t)o * QDIM);
        float acc = 0.f;
#pragma unroll
        for (int qq = 0; qq < QDIM / 4; qq++) {
            float4 wv = w[qq];
            acc += wv.x * xs[qq * 4 + 0] + wv.y * xs[qq * 4 + 1]
                 + wv.z * xs[qq * 4 + 2] + wv.w * xs[qq * 4 + 3];
        }
        out[(size_t)b * ODIM + o] = fmaxf(acc + b3[o], 0.f);
    }
}

// ============================================================================
extern "C" void kernel_launch(void* const* d_in, const int* in_sizes, int n_in,
                              void* d_out, int out_size)
{
    const float* data = (const float*)d_in[0];
    /* d_in[1] = seq_len: unused by the reference */
    const float* W1 = (const float*)d_in[2];
    const float* b1 = (const float*)d_in[3];
    const float* W2 = (const float*)d_in[4];
    const float* b2 = (const float*)d_in[5];
    const float* W3 = (const float*)d_in[6];
    const float* b3 = (const float*)d_in[7];
    float* out = (float*)d_out;

    __half *dataH, *W12h, *QKh, *KTh, *EH;
    float *B12, *RS, *XMAX;
    cudaGetSymbolAddress((void**)&dataH, g_dataH);
    cudaGetSymbolAddress((void**)&W12h, g_W12h);
    cudaGetSymbolAddress((void**)&B12,  g_B12);
    cudaGetSymbolAddress((void**)&QKh,  g_QKh);
    cudaGetSymbolAddress((void**)&KTh,  g_KTh);
    cudaGetSymbolAddress((void**)&EH,   g_EH);
    cudaGetSymbolAddress((void**)&RS,   g_RS);
    cudaGetSymbolAddress((void**)&XMAX, g_XMAX);

    const int SMEM = STAGES * 10240 * 2;   // 81920 B
    cudaFuncSetAttribute(hgemm<2>, cudaFuncAttributeMaxDynamicSharedMemorySize, SMEM);
    cudaFuncSetAttribute(hgemm<3>, cudaFuncAttributeMaxDynamicSharedMemorySize, SMEM);
    cudaFuncSetAttribute(hgemm<4>, cudaFuncAttributeMaxDynamicSharedMemorySize, SMEM);

    const size_t strQK = (size_t)SS * 2 * QDIM;   // per-batch stride in QKh
    const size_t strKT = (size_t)QDIM * SS;
    const size_t strSC = (size_t)SS * SS;
    // E = exp(score/16) = exp2(score * log2e/16)
    const float  exp2_scale = 1.4426950408889634f / 16.0f;

    // 0) convert inputs to fp16; init RS=0, XMAX=-inf, B12=[b1;b2]
    const size_t nd = (size_t)BB * SS * DD;
    f2h_kernel<<<(unsigned)(nd / (256 * 8)), 256>>>(data, dataH, nd);
    f2h_kernel<<<(QDIM * DD) / (256 * 8), 256>>>(W1, W12h, QDIM * DD);
    f2h_kernel<<<(QDIM * DD) / (256 * 8), 256>>>(W2, W12h + QDIM * DD, QDIM * DD);
    init_aux<<<74, 256>>>(RS, XMAX, b1, b2, B12);

    // 1) QK = data @ [W1;W2]^T + [b1;b2] -> fp16 [BS][512]; K part also -> KTh
    hgemm<2><<<dim3(512 / 128, (BB * SS) / 128, 1), 256, SMEM>>>(
        dataH, W12h, B12, QKh, KTh, nullptr, nullptr,
        DD, DD, 2 * QDIM, DD, 1.0f, 0, 0, 0);

    // 2) E[b] = exp2((K[b] @ Q[b]^T) * log2e/16) -> fp16, rowsums into RS
    hgemm<3><<<dim3(SS / 128, SS / 128, BB), 256, SMEM>>>(
        QKh + 256, QKh, nullptr, EH, nullptr, RS, nullptr,
        2 * QDIM, 2 * QDIM, SS, QDIM, exp2_scale, strQK, strQK, strSC);

    // 3) X[q,s] = (KT[b] @ E[b]^T) / RS[b][s]; fused max over s -> XMAX
    hgemm<4><<<dim3(SS / 128, QDIM / 128, BB), 256, SMEM>>>(
        KTh, EH, nullptr, nullptr, nullptr, RS, XMAX,
        SS, SS, SS, SS, 1.0f, strKT, strSC, 0);

    // 4) out = relu(xmax @ W3^T + b3)
    final_head<<<BB, 256>>>(W3, b3, out);
}

// round 15
// speedup vs baseline: 1.4340x; 1.0049x over previous
#include <cuda_runtime.h>
#include <cuda_fp16.h>
#include <cstdint>

#define BB  32
#define SS  2048
#define DD  768
#define QDIM 256
#define ODIM 1024
#define STAGES 4

// -------- scratch (allocation-free: __device__ globals) --------
__device__ __half g_dataH[(size_t)BB * SS * DD];
__device__ __half g_W12h[2 * QDIM * DD];           // [W1; W2] rows 0-255 / 256-511
__device__ float  g_B12[2 * QDIM];                 // [b1; b2]
__device__ __half g_QKh[(size_t)BB * SS * 2 * QDIM]; // per row: Q[0:256] K[256:512]
__device__ __half g_KTh[(size_t)BB * QDIM * SS];   // K transposed [b][q][s]
__device__ __half g_EH [(size_t)BB * SS * SS];     // exp(scores) fp16 (256 MB)
__device__ float  g_RS [BB * SS];                  // row sums of exp
__device__ float  g_XMAX[BB * QDIM];               // fused maxpool result

__device__ __forceinline__ uint32_t smem_u32(const void* p) {
    uint32_t a;
    asm("{ .reg .u64 t; cvta.to.shared.u64 t, %1; cvt.u32.u64 %0, t; }" : "=r"(a) : "l"(p));
    return a;
}
__device__ __forceinline__ void cp16(uint32_t dst, const void* src) {
    asm volatile("cp.async.cg.shared.global [%0], [%1], 16;" :: "r"(dst), "l"(src));
}
#define CP_COMMIT() asm volatile("cp.async.commit_group;" ::: "memory")
#define CP_WAIT(n)  asm volatile("cp.async.wait_group %0;" :: "n"(n) : "memory")

__device__ __forceinline__ void ldsm4(uint32_t& r0, uint32_t& r1, uint32_t& r2,
                                      uint32_t& r3, uint32_t addr) {
    asm volatile("ldmatrix.sync.aligned.m8n8.x4.shared.b16 {%0,%1,%2,%3}, [%4];"
                 : "=r"(r0), "=r"(r1), "=r"(r2), "=r"(r3) : "r"(addr));
}

__device__ __forceinline__ void mma16(float* d, const uint32_t* a, const uint32_t* b) {
    asm("mma.sync.aligned.m16n8k16.row.col.f32.f16.f16.f32 "
        "{%0,%1,%2,%3}, {%4,%5,%6,%7}, {%8,%9}, {%0,%1,%2,%3};"
        : "+f"(d[0]), "+f"(d[1]), "+f"(d[2]), "+f"(d[3])
        : "r"(a[0]), "r"(a[1]), "r"(a[2]), "r"(a[3]), "r"(b[0]), "r"(b[1]));
}

// two fp16 exponentials (base-2) in one MUFU op
__device__ __forceinline__ uint32_t ex2_h2(float x, float y) {
    __half2 h = __floats2half2_rn(x, y);
    uint32_t r;
    asm("ex2.approx.f16x2 %0, %1;" : "=r"(r) : "r"(*(uint32_t*)&h));
    return r;
}

// exact, order-independent float atomic max (init must be -inf)
__device__ __forceinline__ void atomicMaxF(float* a, float v) {
    if (v >= 0.f) atomicMax((int*)a, __float_as_int(v));
    else          atomicMin((unsigned int*)a, __float_as_uint(v));
}

// ============================================================================
// fp16 NT GEMM, cp.async 4-stage pipeline + ldmatrix fragment loads.
// CTA 128x128, k-chunk 32, 256 thr (8 warps 2x4), warp tile 64x32.
// A [M,K], B [N,K] fp16 row-major.
//   EPI=2: C fp16 + bias; if bn>=256 ALSO CT fp16 transposed per-batch
//          [QDIM][SS] at q = n-256 (merged QK projection)
//   EPI=3: C fp16 = exp2(acc*scale)  (scale carries log2e factor);
//          per-row sums (of the stored fp16 values) atomically added to
//          aux[b*SS+m]
//   EPI=4: no C store; X[m,n] = acc / aux[b*SS+n]; row-max over n fused:
//          atomicMaxF into xmax[b*QDIM+m]
// Smem rows padded to 40 halves (80B): conflict-free ldmatrix.
// Requires M%128==0, N%128==0, kdim%32==0.
// ============================================================================
template <int EPI>
__global__ __launch_bounds__(256, 2) void hgemm(
    const __half* __restrict__ A, const __half* __restrict__ B,
    const float* __restrict__ bias, void* __restrict__ Cv,
    __half* __restrict__ CT, float* __restrict__ aux, float* __restrict__ xmax,
    int lda, int ldb, int ldc, int kdim, float scale,
    size_t sA, size_t sB, size_t sC)
{
    extern __shared__ __half sm[];
    A += (size_t)blockIdx.z * sA;
    B += (size_t)blockIdx.z * sB;
    const int bm = blockIdx.y * 128;
    const int bn = blockIdx.x * 128;

    const int tid = threadIdx.x;
    const int lane = tid & 31, wid = tid >> 5;
    const int wm = wid & 1, wn = wid >> 1;      // warp 64m x 32n
    const int qd = lane >> 2, cc = lane & 3;

    // loader: thread covers row = tid>>1, halves [seg, seg+16)
    const int lrow = tid >> 1;
    const int lseg = (tid & 1) * 16;
    const __half* pa = A + (size_t)(bm + lrow) * lda + lseg;
    const __half* pb = B + (size_t)(bn + lrow) * ldb + lseg;
    const uint32_t smb = smem_u32(sm);
    const uint32_t dA = smb + (uint32_t)(lrow * 40 + lseg) * 2;
    const uint32_t dB = dA + 5120 * 2;
    const uint32_t STG = 10240 * 2;             // bytes per stage (A+B)

    // ldmatrix per-lane offsets (relative to stage base, ks=0)
    uint32_t aoff[4], boff[2];
#pragma unroll
    for (int mt = 0; mt < 4; mt++)
        aoff[mt] = (uint32_t)(((wm * 64 + mt * 16 + (lane & 7) + (lane & 8)) * 40
                               + ((lane >> 4) * 8)) * 2);
#pragma unroll
    for (int np = 0; np < 2; np++)
        boff[np] = (uint32_t)(5120 * 2
                   + ((wn * 32 + np * 16 + (lane & 7) + ((lane >> 4) * 8)) * 40
                      + (lane & 8)) * 2);

    float acc[4][4][4];
#pragma unroll
    for (int i = 0; i < 4; i++)
#pragma unroll
        for (int j = 0; j < 4; j++)
#pragma unroll
            for (int r = 0; r < 4; r++) acc[i][j][r] = 0.f;

    const int nc = kdim >> 5;

    // prologue: stages 0..STAGES-2
#pragma unroll
    for (int s = 0; s < STAGES - 1; s++) {
        if (s < nc) {
            const size_t k0 = (size_t)s * 32;
            const uint32_t da = dA + s * STG, db = dB + s * STG;
            cp16(da,      pa + k0);
            cp16(da + 16, pa + k0 + 8);
            cp16(db,      pb + k0);
            cp16(db + 16, pb + k0 + 8);
        }
        CP_COMMIT();
    }

    for (int ch = 0; ch < nc; ch++) {
        CP_WAIT(STAGES - 2);
        __syncthreads();   // stage ch ready; everyone done reading stage ch-1

        // refill the stage freed by chunk ch-1
        {
            const int nxt = ch + STAGES - 1;
            if (nxt < nc) {
                const int st = nxt & (STAGES - 1);
                const size_t k0 = (size_t)nxt * 32;
                const uint32_t da = dA + st * STG, db = dB + st * STG;
                cp16(da,      pa + k0);
                cp16(da + 16, pa + k0 + 8);
                cp16(db,      pb + k0);
                cp16(db + 16, pb + k0 + 8);
            }
            CP_COMMIT();
        }

        const uint32_t sa = smb + (uint32_t)(ch & (STAGES - 1)) * STG;
#pragma unroll
        for (int ks = 0; ks < 2; ks++) {
            uint32_t af[4][4], bf[4][2];
#pragma unroll
            for (int mt = 0; mt < 4; mt++)
                ldsm4(af[mt][0], af[mt][1], af[mt][2], af[mt][3],
                      sa + aoff[mt] + ks * 32);
#pragma unroll
            for (int np = 0; np < 2; np++)
                ldsm4(bf[2 * np][0], bf[2 * np][1], bf[2 * np + 1][0],
                      bf[2 * np + 1][1], sa + boff[np] + ks * 32);
#pragma unroll
            for (int mt = 0; mt < 4; mt++)
#pragma unroll
                for (int nt = 0; nt < 4; nt++)
                    mma16(acc[mt][nt], af[mt], bf[nt]);
        }
    }

    // ---- epilogue ----
    float inv[4][2];
    if (EPI == 4) {
#pragma unroll
        for (int nt = 0; nt < 4; nt++) {
            const int n0 = bn + wn * 32 + nt * 8 + cc * 2;
            inv[nt][0] = 1.0f / __ldg(&aux[blockIdx.z * SS + n0]);
            inv[nt][1] = 1.0f / __ldg(&aux[blockIdx.z * SS + n0 + 1]);
        }
    }
    float* srs = (float*)sm;   // EPI==3: per-CTA row sums (128 floats)
    if (EPI == 3) {
        __syncthreads();       // all warps done reading pipeline smem
        if (tid < 128) srs[tid] = 0.f;
        __syncthreads();
    }

#pragma unroll
    for (int mt = 0; mt < 4; mt++) {
        const int m0 = bm + wm * 64 + mt * 16 + qd;
        float rs0 = 0.f, rs1 = 0.f;               // EPI==3 row sums
        float mx0 = -INFINITY, mx1 = -INFINITY;   // EPI==4 row maxes
#pragma unroll
        for (int nt = 0; nt < 4; nt++) {
            const int n0 = bn + wn * 32 + nt * 8 + cc * 2;
            float c0 = acc[mt][nt][0] * scale;
            float c1 = acc[mt][nt][1] * scale;
            float c2 = acc[mt][nt][2] * scale;
            float c3 = acc[mt][nt][3] * scale;
            if (EPI == 4) {
                c0 *= inv[nt][0]; c1 *= inv[nt][1];
                c2 *= inv[nt][0]; c3 *= inv[nt][1];
                mx0 = fmaxf(mx0, fmaxf(c0, c1));
                mx1 = fmaxf(mx1, fmaxf(c2, c3));
            } else if (EPI == 3) {
                // E = exp2(score * log2e / 16) computed 2-at-a-time on MUFU
                const uint32_t e0 = ex2_h2(c0, c1);
                const uint32_t e1 = ex2_h2(c2, c3);
                const float2 f0 = __half22float2(*(const __half2*)&e0);
                const float2 f1 = __half22float2(*(const __half2*)&e1);
                rs0 += f0.x + f0.y;
                rs1 += f1.x + f1.y;
                __half* Ch = (__half*)Cv + (size_t)blockIdx.z * sC;
                *(uint32_t*)(Ch + (size_t)m0 * ldc + n0)       = e0;
                *(uint32_t*)(Ch + (size_t)(m0 + 8) * ldc + n0) = e1;
            } else {  // EPI == 2: merged QK projection
                const float bx = bias[n0], by = bias[n0 + 1];
                c0 += bx; c1 += by; c2 += bx; c3 += by;
                __half2 h0 = __floats2half2_rn(c0, c1);
                __half2 h1 = __floats2half2_rn(c2, c3);
                __half* Ch = (__half*)Cv + (size_t)blockIdx.z * sC;
                *(__half2*)(Ch + (size_t)m0 * ldc + n0)       = h0;
                *(__half2*)(Ch + (size_t)(m0 + 8) * ldc + n0) = h1;
                if (bn >= 256) {   // K columns -> transposed copy
                    const int b0 = m0 >> 11, s0 = m0 & (SS - 1);
                    __half* t = CT + ((size_t)b0 * QDIM + (n0 - 256)) * SS + s0;
                    t[0]      = __low2half(h0);
                    t[SS]     = __high2half(h0);
                    t[8]      = __low2half(h1);
                    t[SS + 8] = __high2half(h1);
                }
            }
        }
        if (EPI == 3) {
            rs0 += __shfl_xor_sync(0xffffffffu, rs0, 1);
            rs0 += __shfl_xor_sync(0xffffffffu, rs0, 2);
            rs1 += __shfl_xor_sync(0xffffffffu, rs1, 1);
            rs1 += __shfl_xor_sync(0xffffffffu, rs1, 2);
            if (cc == 0) {
                atomicAdd(&srs[wm * 64 + mt * 16 + qd],     rs0);
                atomicAdd(&srs[wm * 64 + mt * 16 + qd + 8], rs1);
            }
        }
        if (EPI == 4) {
            mx0 = fmaxf(mx0, __shfl_xor_sync(0xffffffffu, mx0, 1));
            mx0 = fmaxf(mx0, __shfl_xor_sync(0xffffffffu, mx0, 2));
            mx1 = fmaxf(mx1, __shfl_xor_sync(0xffffffffu, mx1, 1));
            mx1 = fmaxf(mx1, __shfl_xor_sync(0xffffffffu, mx1, 2));
            if (cc == 0) {
                atomicMaxF(&xmax[blockIdx.z * QDIM + m0],     mx0);
                atomicMaxF(&xmax[blockIdx.z * QDIM + m0 + 8], mx1);
            }
        }
    }
    if (EPI == 3) {
        __syncthreads();
        if (tid < 128) atomicAdd(&aux[blockIdx.z * SS + bm + tid], srs[tid]);
    }
}

// ============================================================================
// Unified preamble: ONE launch does all fp32->fp16 conversions + init.
//   blocks [0, NB_DATA)                 : data -> dataH (8 floats/thread)
//   blocks [NB_DATA, +NB_W)             : W1 -> W12h[0:]
//   blocks [NB_DATA+NB_W, +NB_W)        : W2 -> W12h[QDIM*DD:]
//   next 64 blocks                      : RS = 0
//   next 8 blocks                       : XMAX = -inf
//   next 2 blocks                       : B12 = [b1; b2]
// ============================================================================
#define NB_DATA ((int)(((size_t)BB * SS * DD) / 2048))   // 24576
#define NB_W    ((QDIM * DD) / 2048)                     // 96

__device__ __forceinline__ void f2h_block(const float* __restrict__ s,
                                          __half* __restrict__ d, int blk)
{
    const size_t i = ((size_t)blk * 256 + threadIdx.x) * 8;
    float4 a = *(const float4*)(s + i);
    float4 b = *(const float4*)(s + i + 4);
    uint4 o;
    __half2 h;
    h = __floats2half2_rn(a.x, a.y); o.x = *(uint32_t*)&h;
    h = __floats2half2_rn(a.z, a.w); o.y = *(uint32_t*)&h;
    h = __floats2half2_rn(b.x, b.y); o.z = *(uint32_t*)&h;
    h = __floats2half2_rn(b.z, b.w); o.w = *(uint32_t*)&h;
    *(uint4*)(d + i) = o;
}

__global__ __launch_bounds__(256) void preamble(
    const float* __restrict__ data,
    const float* __restrict__ W1, const float* __restrict__ b1,
    const float* __restrict__ W2, const float* __restrict__ b2,
    __half* __restrict__ dataH, __half* __restrict__ W12h,
    float* __restrict__ b12, float* __restrict__ rs, float* __restrict__ xmax)
{
    int b = blockIdx.x;
    if (b < NB_DATA) { f2h_block(data, dataH, b); return; }
    b -= NB_DATA;
    if (b < NB_W) { f2h_block(W1, W12h, b); return; }
    b -= NB_W;
    if (b < NB_W) { f2h_block(W2, W12h + QDIM * DD, b); return; }
    b -= NB_W;
    if (b < 64) {
        const int i = b * 1024 + threadIdx.x * 4;
        *(float4*)(rs + i) = make_float4(0.f, 0.f, 0.f, 0.f);
        return;
    }
    b -= 64;
    if (b < 8) {
        const int i = b * 1024 + threadIdx.x * 4;
        const float ninf = -INFINITY;
        *(float4*)(xmax + i) = make_float4(ninf, ninf, ninf, ninf);
        return;
    }
    b -= 8;
    if (b == 0) b12[threadIdx.x] = b1[threadIdx.x];
    else        b12[256 + threadIdx.x] = b2[threadIdx.x];
}

// ============================================================================
__global__ __launch_bounds__(256) void final_head(
    const float* __restrict__ W3, const float* __restrict__ b3,
    float* __restrict__ out)
{
    const int b = blockIdx.x;
    const int tid = threadIdx.x;
    __shared__ float xs[QDIM];
    xs[tid] = g_XMAX[b * QDIM + tid];
    __syncthreads();

#pragma unroll
    for (int kk = 0; kk < 4; kk++) {
        const int o = tid + kk * 256;
        const float4* w = (const float4*)(W3 + (size_t)o * QDIM);
        float acc = 0.f;
#pragma unroll
        for (int qq = 0; qq < QDIM / 4; qq++) {
            float4 wv = w[qq];
            acc += wv.x * xs[qq * 4 + 0] + wv.y * xs[qq * 4 + 1]
                 + wv.z * xs[qq * 4 + 2] + wv.w * xs[qq * 4 + 3];
        }
        out[(size_t)b * ODIM + o] = fmaxf(acc + b3[o], 0.f);
    }
}

// ============================================================================
extern "C" void kernel_launch(void* const* d_in, const int* in_sizes, int n_in,
                              void* d_out, int out_size)
{
    const float* data = (const float*)d_in[0];
    /* d_in[1] = seq_len: unused by the reference */
    const float* W1 = (const float*)d_in[2];
    const float* b1 = (const float*)d_in[3];
    const float* W2 = (const float*)d_in[4];
    const float* b2 = (const float*)d_in[5];
    const float* W3 = (const float*)d_in[6];
    const float* b3 = (const float*)d_in[7];
    float* out = (float*)d_out;

    __half *dataH, *W12h, *QKh, *KTh, *EH;
    float *B12, *RS, *XMAX;
    cudaGetSymbolAddress((void**)&dataH, g_dataH);
    cudaGetSymbolAddress((void**)&W12h, g_W12h);
    cudaGetSymbolAddress((void**)&B12,  g_B12);
    cudaGetSymbolAddress((void**)&QKh,  g_QKh);
    cudaGetSymbolAddress((void**)&KTh,  g_KTh);
    cudaGetSymbolAddress((void**)&EH,   g_EH);
    cudaGetSymbolAddress((void**)&RS,   g_RS);
    cudaGetSymbolAddress((void**)&XMAX, g_XMAX);

    const int SMEM = STAGES * 10240 * 2;   // 81920 B
    cudaFuncSetAttribute(hgemm<2>, cudaFuncAttributeMaxDynamicSharedMemorySize, SMEM);
    cudaFuncSetAttribute(hgemm<3>, cudaFuncAttributeMaxDynamicSharedMemorySize, SMEM);
    cudaFuncSetAttribute(hgemm<4>, cudaFuncAttributeMaxDynamicSharedMemorySize, SMEM);

    const size_t strQK = (size_t)SS * 2 * QDIM;   // per-batch stride in QKh
    const size_t strKT = (size_t)QDIM * SS;
    const size_t strSC = (size_t)SS * SS;
    // E = exp(score/16) = exp2(score * log2e/16)
    const float  exp2_scale = 1.4426950408889634f / 16.0f;

    // 0) single preamble launch: conversions + init
    const int NB_TOTAL = NB_DATA + 2 * NB_W + 64 + 8 + 2;
    preamble<<<NB_TOTAL, 256>>>(data, W1, b1, W2, b2,
                                dataH, W12h, B12, RS, XMAX);

    // 1) QK = data @ [W1;W2]^T + [b1;b2] -> fp16 [BS][512]; K part also -> KTh
    hgemm<2><<<dim3(512 / 128, (BB * SS) / 128, 1), 256, SMEM>>>(
        dataH, W12h, B12, QKh, KTh, nullptr, nullptr,
        DD, DD, 2 * QDIM, DD, 1.0f, 0, 0, 0);

    // 2) E[b] = exp2((K[b] @ Q[b]^T) * log2e/16) -> fp16, rowsums into RS
    hgemm<3><<<dim3(SS / 128, SS / 128, BB), 256, SMEM>>>(
        QKh + 256, QKh, nullptr, EH, nullptr, RS, nullptr,
        2 * QDIM, 2 * QDIM, SS, QDIM, exp2_scale, strQK, strQK, strSC);

    // 3) X[q,s] = (KT[b] @ E[b]^T) / RS[b][s]; fused max over s -> XMAX
    hgemm<4><<<dim3(SS / 128, QDIM / 128, BB), 256, SMEM>>>(
        KTh, EH, nullptr, nullptr, nullptr, RS, XMAX,
        SS, SS, SS, SS, 1.0f, strKT, strSC, 0);

    // 4) out = relu(xmax @ W3^T + b3)
    final_head<<<BB, 256>>>(W3, b3, out);
}

// round 16
// speedup vs baseline: 1.4345x; 1.0003x over previous
#include <cuda_runtime.h>
#include <cuda_fp16.h>
#include <cstdint>

#define BB  32
#define SS  2048
#define DD  768
#define QDIM 256
#define ODIM 1024
#define STAGES 4

// -------- scratch (allocation-free: __device__ globals) --------
__device__ __half g_dataH[(size_t)BB * SS * DD];
__device__ __half g_W12h[2 * QDIM * DD];           // [W1*log2e/16; W2]
__device__ float  g_B12[2 * QDIM];                 // [b1*log2e/16; b2]
__device__ __half g_QKh[(size_t)BB * SS * 2 * QDIM]; // per row: Q'[0:256] K[256:512]
__device__ __half g_KTh[(size_t)BB * QDIM * SS];   // K transposed [b][q][s]
__device__ __half g_EH [(size_t)BB * SS * SS];     // exp(scores) fp16 (256 MB)
__device__ float  g_RS [BB * SS];                  // row sums of exp
__device__ float  g_XMAX[BB * QDIM];               // fused maxpool result

__device__ __forceinline__ uint32_t smem_u32(const void* p) {
    uint32_t a;
    asm("{ .reg .u64 t; cvta.to.shared.u64 t, %1; cvt.u32.u64 %0, t; }" : "=r"(a) : "l"(p));
    return a;
}
__device__ __forceinline__ void cp16(uint32_t dst, const void* src) {
    asm volatile("cp.async.cg.shared.global [%0], [%1], 16;" :: "r"(dst), "l"(src));
}
#define CP_COMMIT() asm volatile("cp.async.commit_group;" ::: "memory")
#define CP_WAIT(n)  asm volatile("cp.async.wait_group %0;" :: "n"(n) : "memory")

__device__ __forceinline__ void ldsm4(uint32_t& r0, uint32_t& r1, uint32_t& r2,
                                      uint32_t& r3, uint32_t addr) {
    asm volatile("ldmatrix.sync.aligned.m8n8.x4.shared.b16 {%0,%1,%2,%3}, [%4];"
                 : "=r"(r0), "=r"(r1), "=r"(r2), "=r"(r3) : "r"(addr));
}

__device__ __forceinline__ void mma16(float* d, const uint32_t* a, const uint32_t* b) {
    asm("mma.sync.aligned.m16n8k16.row.col.f32.f16.f16.f32 "
        "{%0,%1,%2,%3}, {%4,%5,%6,%7}, {%8,%9}, {%0,%1,%2,%3};"
        : "+f"(d[0]), "+f"(d[1]), "+f"(d[2]), "+f"(d[3])
        : "r"(a[0]), "r"(a[1]), "r"(a[2]), "r"(a[3]), "r"(b[0]), "r"(b[1]));
}

// two fp16 exponentials (base-2) in one MUFU op
__device__ __forceinline__ uint32_t ex2_h2(float x, float y) {
    __half2 h = __floats2half2_rn(x, y);
    uint32_t r;
    asm("ex2.approx.f16x2 %0, %1;" : "=r"(r) : "r"(*(uint32_t*)&h));
    return r;
}

// exact, order-independent float atomic max (init must be -inf)
__device__ __forceinline__ void atomicMaxF(float* a, float v) {
    if (v >= 0.f) atomicMax((int*)a, __float_as_int(v));
    else          atomicMin((unsigned int*)a, __float_as_uint(v));
}

// ============================================================================
// fp16 NT GEMM, cp.async 4-stage pipeline + ldmatrix fragment loads.
// CTA 128x128, k-chunk 32, 256 thr (8 warps 2x4), warp tile 64x32.
// A [M,K], B [N,K] fp16 row-major.  (no epilogue scale: folded into weights)
//   EPI=2: C fp16 + bias; if bn>=256 ALSO CT fp16 transposed per-batch
//          [QDIM][SS] at q = n-256 (merged QK projection)
//   EPI=3: C fp16 = exp2(acc)  (log2e/16 pre-folded into Q' weights);
//          per-row sums of stored fp16 values atomically added to aux[b*SS+m]
//   EPI=4: no C store; X[m,n] = acc / aux[b*SS+n]; row-max over n fused:
//          atomicMaxF into xmax[b*QDIM+m]
// Smem rows padded to 40 halves (80B): conflict-free ldmatrix.
// Requires M%128==0, N%128==0, kdim%32==0.
// ============================================================================
template <int EPI>
__global__ __launch_bounds__(256, 2) void hgemm(
    const __half* __restrict__ A, const __half* __restrict__ B,
    const float* __restrict__ bias, void* __restrict__ Cv,
    __half* __restrict__ CT, float* __restrict__ aux, float* __restrict__ xmax,
    int lda, int ldb, int ldc, int kdim,
    size_t sA, size_t sB, size_t sC)
{
    extern __shared__ __half sm[];
    A += (size_t)blockIdx.z * sA;
    B += (size_t)blockIdx.z * sB;
    const int bm = blockIdx.y * 128;
    const int bn = blockIdx.x * 128;

    const int tid = threadIdx.x;
    const int lane = tid & 31, wid = tid >> 5;
    const int wm = wid & 1, wn = wid >> 1;      // warp 64m x 32n
    const int qd = lane >> 2, cc = lane & 3;

    // loader: thread covers row = tid>>1, halves [seg, seg+16)
    const int lrow = tid >> 1;
    const int lseg = (tid & 1) * 16;
    const __half* pa = A + (size_t)(bm + lrow) * lda + lseg;
    const __half* pb = B + (size_t)(bn + lrow) * ldb + lseg;
    const uint32_t smb = smem_u32(sm);
    const uint32_t dA = smb + (uint32_t)(lrow * 40 + lseg) * 2;
    const uint32_t dB = dA + 5120 * 2;
    const uint32_t STG = 10240 * 2;             // bytes per stage (A+B)

    // ldmatrix per-lane offsets (relative to stage base, ks=0)
    uint32_t aoff[4], boff[2];
#pragma unroll
    for (int mt = 0; mt < 4; mt++)
        aoff[mt] = (uint32_t)(((wm * 64 + mt * 16 + (lane & 7) + (lane & 8)) * 40
                               + ((lane >> 4) * 8)) * 2);
#pragma unroll
    for (int np = 0; np < 2; np++)
        boff[np] = (uint32_t)(5120 * 2
                   + ((wn * 32 + np * 16 + (lane & 7) + ((lane >> 4) * 8)) * 40
                      + (lane & 8)) * 2);

    float acc[4][4][4];
#pragma unroll
    for (int i = 0; i < 4; i++)
#pragma unroll
        for (int j = 0; j < 4; j++)
#pragma unroll
            for (int r = 0; r < 4; r++) acc[i][j][r] = 0.f;

    const int nc = kdim >> 5;

    // prologue: stages 0..STAGES-2
#pragma unroll
    for (int s = 0; s < STAGES - 1; s++) {
        if (s < nc) {
            const size_t k0 = (size_t)s * 32;
            const uint32_t da = dA + s * STG, db = dB + s * STG;
            cp16(da,      pa + k0);
            cp16(da + 16, pa + k0 + 8);
            cp16(db,      pb + k0);
            cp16(db + 16, pb + k0 + 8);
        }
        CP_COMMIT();
    }

    for (int ch = 0; ch < nc; ch++) {
        CP_WAIT(STAGES - 2);
        __syncthreads();   // stage ch ready; everyone done reading stage ch-1

        // refill the stage freed by chunk ch-1
        {
            const int nxt = ch + STAGES - 1;
            if (nxt < nc) {
                const int st = nxt & (STAGES - 1);
                const size_t k0 = (size_t)nxt * 32;
                const uint32_t da = dA + st * STG, db = dB + st * STG;
                cp16(da,      pa + k0);
                cp16(da + 16, pa + k0 + 8);
                cp16(db,      pb + k0);
                cp16(db + 16, pb + k0 + 8);
            }
            CP_COMMIT();
        }

        const uint32_t sa = smb + (uint32_t)(ch & (STAGES - 1)) * STG;
#pragma unroll
        for (int ks = 0; ks < 2; ks++) {
            uint32_t af[4][4], bf[4][2];
#pragma unroll
            for (int mt = 0; mt < 4; mt++)
                ldsm4(af[mt][0], af[mt][1], af[mt][2], af[mt][3],
                      sa + aoff[mt] + ks * 32);
#pragma unroll
            for (int np = 0; np < 2; np++)
                ldsm4(bf[2 * np][0], bf[2 * np][1], bf[2 * np + 1][0],
                      bf[2 * np + 1][1], sa + boff[np] + ks * 32);
#pragma unroll
            for (int mt = 0; mt < 4; mt++)
#pragma unroll
                for (int nt = 0; nt < 4; nt++)
                    mma16(acc[mt][nt], af[mt], bf[nt]);
        }
    }

    // ---- epilogue ----
    float inv[4][2];
    if (EPI == 4) {
#pragma unroll
        for (int nt = 0; nt < 4; nt++) {
            const int n0 = bn + wn * 32 + nt * 8 + cc * 2;
            inv[nt][0] = 1.0f / __ldg(&aux[blockIdx.z * SS + n0]);
            inv[nt][1] = 1.0f / __ldg(&aux[blockIdx.z * SS + n0 + 1]);
        }
    }
    float* srs = (float*)sm;   // EPI==3: per-CTA row sums (128 floats)
    if (EPI == 3) {
        __syncthreads();       // all warps done reading pipeline smem
        if (tid < 128) srs[tid] = 0.f;
        __syncthreads();
    }

#pragma unroll
    for (int mt = 0; mt < 4; mt++) {
        const int m0 = bm + wm * 64 + mt * 16 + qd;
        float rs0 = 0.f, rs1 = 0.f;               // EPI==3 row sums
        float mx0 = -INFINITY, mx1 = -INFINITY;   // EPI==4 row maxes
#pragma unroll
        for (int nt = 0; nt < 4; nt++) {
            const int n0 = bn + wn * 32 + nt * 8 + cc * 2;
            const float c0 = acc[mt][nt][0];
            const float c1 = acc[mt][nt][1];
            const float c2 = acc[mt][nt][2];
            const float c3 = acc[mt][nt][3];
            if (EPI == 4) {
                const float x0 = c0 * inv[nt][0], x1 = c1 * inv[nt][1];
                const float x2 = c2 * inv[nt][0], x3 = c3 * inv[nt][1];
                mx0 = fmaxf(mx0, fmaxf(x0, x1));
                mx1 = fmaxf(mx1, fmaxf(x2, x3));
            } else if (EPI == 3) {
                // acc already in exp2 domain (Q' pre-scaled by log2e/16)
                const uint32_t e0 = ex2_h2(c0, c1);
                const uint32_t e1 = ex2_h2(c2, c3);
                const float2 f0 = __half22float2(*(const __half2*)&e0);
                const float2 f1 = __half22float2(*(const __half2*)&e1);
                rs0 += f0.x + f0.y;
                rs1 += f1.x + f1.y;
                __half* Ch = (__half*)Cv + (size_t)blockIdx.z * sC;
                *(uint32_t*)(Ch + (size_t)m0 * ldc + n0)       = e0;
                *(uint32_t*)(Ch + (size_t)(m0 + 8) * ldc + n0) = e1;
            } else {  // EPI == 2: merged QK projection
                const float bx = bias[n0], by = bias[n0 + 1];
                __half2 h0 = __floats2half2_rn(c0 + bx, c1 + by);
                __half2 h1 = __floats2half2_rn(c2 + bx, c3 + by);
                __half* Ch = (__half*)Cv + (size_t)blockIdx.z * sC;
                *(__half2*)(Ch + (size_t)m0 * ldc + n0)       = h0;
                *(__half2*)(Ch + (size_t)(m0 + 8) * ldc + n0) = h1;
                if (bn >= 256) {   // K columns -> transposed copy
                    const int b0 = m0 >> 11, s0 = m0 & (SS - 1);
                    __half* t = CT + ((size_t)b0 * QDIM + (n0 - 256)) * SS + s0;
                    t[0]      = __low2half(h0);
                    t[SS]     = __high2half(h0);
                    t[8]      = __low2half(h1);
                    t[SS + 8] = __high2half(h1);
                }
            }
        }
        if (EPI == 3) {
            rs0 += __shfl_xor_sync(0xffffffffu, rs0, 1);
            rs0 += __shfl_xor_sync(0xffffffffu, rs0, 2);
            rs1 += __shfl_xor_sync(0xffffffffu, rs1, 1);
            rs1 += __shfl_xor_sync(0xffffffffu, rs1, 2);
            if (cc == 0) {
                atomicAdd(&srs[wm * 64 + mt * 16 + qd],     rs0);
                atomicAdd(&srs[wm * 64 + mt * 16 + qd + 8], rs1);
            }
        }
        if (EPI == 4) {
            mx0 = fmaxf(mx0, __shfl_xor_sync(0xffffffffu, mx0, 1));
            mx0 = fmaxf(mx0, __shfl_xor_sync(0xffffffffu, mx0, 2));
            mx1 = fmaxf(mx1, __shfl_xor_sync(0xffffffffu, mx1, 1));
            mx1 = fmaxf(mx1, __shfl_xor_sync(0xffffffffu, mx1, 2));
            if (cc == 0) {
                atomicMaxF(&xmax[blockIdx.z * QDIM + m0],     mx0);
                atomicMaxF(&xmax[blockIdx.z * QDIM + m0 + 8], mx1);
            }
        }
    }
    if (EPI == 3) {
        __syncthreads();
        if (tid < 128) atomicAdd(&aux[blockIdx.z * SS + bm + tid], srs[tid]);
    }
}

// ============================================================================
// Unified preamble: ONE launch does all fp32->fp16 conversions + init.
//   blocks [0, NB_DATA)          : data -> dataH
//   next NB_W blocks             : W1 * (log2e/16) -> W12h[0:]
//   next NB_W blocks             : W2 -> W12h[QDIM*DD:]
//   next 64 blocks               : RS = 0
//   next 8 blocks                : XMAX = -inf
//   next 2 blocks                : B12 = [b1*(log2e/16); b2]
// ============================================================================
#define NB_DATA ((int)(((size_t)BB * SS * DD) / 2048))   // 24576
#define NB_W    ((QDIM * DD) / 2048)                     // 96
#define QSCALE  (1.4426950408889634f / 16.0f)            // log2e / sqrt(QD)

__device__ __forceinline__ void f2h_block(const float* __restrict__ s,
                                          __half* __restrict__ d, int blk,
                                          float sc)
{
    const size_t i = ((size_t)blk * 256 + threadIdx.x) * 8;
    float4 a = *(const float4*)(s + i);
    float4 b = *(const float4*)(s + i + 4);
    uint4 o;
    __half2 h;
    h = __floats2half2_rn(a.x * sc, a.y * sc); o.x = *(uint32_t*)&h;
    h = __floats2half2_rn(a.z * sc, a.w * sc); o.y = *(uint32_t*)&h;
    h = __floats2half2_rn(b.x * sc, b.y * sc); o.z = *(uint32_t*)&h;
    h = __floats2half2_rn(b.z * sc, b.w * sc); o.w = *(uint32_t*)&h;
    *(uint4*)(d + i) = o;
}

__global__ __launch_bounds__(256) void preamble(
    const float* __restrict__ data,
    const float* __restrict__ W1, const float* __restrict__ b1,
    const float* __restrict__ W2, const float* __restrict__ b2,
    __half* __restrict__ dataH, __half* __restrict__ W12h,
    float* __restrict__ b12, float* __restrict__ rs, float* __restrict__ xmax)
{
    int b = blockIdx.x;
    if (b < NB_DATA) { f2h_block(data, dataH, b, 1.0f); return; }
    b -= NB_DATA;
    if (b < NB_W) { f2h_block(W1, W12h, b, QSCALE); return; }
    b -= NB_W;
    if (b < NB_W) { f2h_block(W2, W12h + QDIM * DD, b, 1.0f); return; }
    b -= NB_W;
    if (b < 64) {
        const int i = b * 1024 + threadIdx.x * 4;
        *(float4*)(rs + i) = make_float4(0.f, 0.f, 0.f, 0.f);
        return;
    }
    b -= 64;
    if (b < 8) {
        const int i = b * 1024 + threadIdx.x * 4;
        const float ninf = -INFINITY;
        *(float4*)(xmax + i) = make_float4(ninf, ninf, ninf, ninf);
        return;
    }
    b -= 8;
    if (b == 0) b12[threadIdx.x] = b1[threadIdx.x] * QSCALE;
    else        b12[256 + threadIdx.x] = b2[threadIdx.x];
}

// ============================================================================
__global__ __launch_bounds__(256) void final_head(
    const float* __restrict__ W3, const float* __restrict__ b3,
    float* __restrict__ out)
{
    const int b = blockIdx.x;
    const int tid = threadIdx.x;
    __shared__ float xs[QDIM];
    xs[tid] = g_XMAX[b * QDIM + tid];
    __syncthreads();

#pragma unroll
    for (int kk = 0; kk < 4; kk++) {
        const int o = tid + kk * 256;
        const float4* w = (const float4*)(W3 + (size_t)o * QDIM);
        float acc = 0.f;
#pragma unroll
        for (int qq = 0; qq < QDIM / 4; qq++) {
            float4 wv = w[qq];
            acc += wv.x * xs[qq * 4 + 0] + wv.y * xs[qq * 4 + 1]
                 + wv.z * xs[qq * 4 + 2] + wv.w * xs[qq * 4 + 3];
        }
        out[(size_t)b * ODIM + o] = fmaxf(acc + b3[o], 0.f);
    }
}

// ============================================================================
extern "C" void kernel_launch(void* const* d_in, const int* in_sizes, int n_in,
                              void* d_out, int out_size)
{
    const float* data = (const float*)d_in[0];
    /* d_in[1] = seq_len: unused by the reference */
    const float* W1 = (const float*)d_in[2];
    const float* b1 = (const float*)d_in[3];
    const float* W2 = (const float*)d_in[4];
    const float* b2 = (const float*)d_in[5];
    const float* W3 = (const float*)d_in[6];
    const float* b3 = (const float*)d_in[7];
    float* out = (float*)d_out;

    __half *dataH, *W12h, *QKh, *KTh, *EH;
    float *B12, *RS, *XMAX;
    cudaGetSymbolAddress((void**)&dataH, g_dataH);
    cudaGetSymbolAddress((void**)&W12h, g_W12h);
    cudaGetSymbolAddress((void**)&B12,  g_B12);
    cudaGetSymbolAddress((void**)&QKh,  g_QKh);
    cudaGetSymbolAddress((void**)&KTh,  g_KTh);
    cudaGetSymbolAddress((void**)&EH,   g_EH);
    cudaGetSymbolAddress((void**)&RS,   g_RS);
    cudaGetSymbolAddress((void**)&XMAX, g_XMAX);

    const int SMEM = STAGES * 10240 * 2;   // 81920 B
    cudaFuncSetAttribute(hgemm<2>, cudaFuncAttributeMaxDynamicSharedMemorySize, SMEM);
    cudaFuncSetAttribute(hgemm<3>, cudaFuncAttributeMaxDynamicSharedMemorySize, SMEM);
    cudaFuncSetAttribute(hgemm<4>, cudaFuncAttributeMaxDynamicSharedMemorySize, SMEM);

    const size_t strQK = (size_t)SS * 2 * QDIM;   // per-batch stride in QKh
    const size_t strKT = (size_t)QDIM * SS;
    const size_t strSC = (size_t)SS * SS;

    // 0) single preamble launch: conversions (Q weights pre-scaled) + init
    const int NB_TOTAL = NB_DATA + 2 * NB_W + 64 + 8 + 2;
    preamble<<<NB_TOTAL, 256>>>(data, W1, b1, W2, b2,
                                dataH, W12h, B12, RS, XMAX);

    // 1) QK = data @ [W1';W2]^T + [b1';b2] -> fp16 [BS][512]; K part -> KTh
    hgemm<2><<<dim3(512 / 128, (BB * SS) / 128, 1), 256, SMEM>>>(
        dataH, W12h, B12, QKh, KTh, nullptr, nullptr,
        DD, DD, 2 * QDIM, DD, 0, 0, 0);

    // 2) E[b] = exp2(K[b] @ Q'[b]^T) -> fp16, rowsums into RS
    hgemm<3><<<dim3(SS / 128, SS / 128, BB), 256, SMEM>>>(
        QKh + 256, QKh, nullptr, EH, nullptr, RS, nullptr,
        2 * QDIM, 2 * QDIM, SS, QDIM, strQK, strQK, strSC);

    // 3) X[q,s] = (KT[b] @ E[b]^T) / RS[b][s]; fused max over s -> XMAX
    hgemm<4><<<dim3(SS / 128, QDIM / 128, BB), 256, SMEM>>>(
        KTh, EH, nullptr, nullptr, nullptr, RS, XMAX,
        SS, SS, SS, SS, strKT, strSC, 0);

    // 4) out = relu(xmax @ W3^T + b3)
    final_head<<<BB, 256>>>(W3, b3, out);
}